// round 8
// baseline (speedup 1.0000x reference)
#include <cuda_runtime.h>
#include <cuda_fp16.h>
#include <math.h>
#include <stdint.h>

#define Bb    4
#define Tt    10
#define Nn    2048
#define Ff    64
#define Hh    128
#define NHEAD 4
#define Dd    32
#define Ee    65536
#define NTOT  8192            // B*N
#define MTOT  81920           // T*NTOT
#define G4H   512             // 4*H
#define EFULL (Ee + NTOT)     // edges + self loops

// ---------------- device scratch (no allocations allowed) ----------------
__device__ __align__(16) __half g_xhi[MTOT * Ff],  g_xlo[MTOT * Ff];
__device__ __align__(16) __half g_wthi[Hh * Ff],   g_wtlo[Hh * Ff];
__device__ __align__(16) __half g_sphi[MTOT * Hh], g_splo[MTOT * Hh];
// LSTM weights, rows interleaved: new row 4d+q = original row q*128+d
__device__ __align__(16) __half g_w0hi[G4H * Hh],  g_w0lo[G4H * Hh];   // W_ih0
__device__ __align__(16) __half g_u0hi[G4H * Hh],  g_u0lo[G4H * Hh];   // W_hh0
__device__ __align__(16) __half g_w1hi[G4H * Hh],  g_w1lo[G4H * Hh];   // W_ih1
__device__ __align__(16) __half g_u1hi[G4H * Hh],  g_u1lo[G4H * Hh];   // W_hh1
// time-ringed recurrent state (slot t read, slot t+1 written)
__device__ __align__(16) __half g_h0hi[(Tt + 1) * NTOT * Hh], g_h0lo[(Tt + 1) * NTOT * Hh];
__device__ __align__(16) __half g_h1hi[(Tt + 1) * NTOT * Hh], g_h1lo[(Tt + 1) * NTOT * Hh];

__device__ float g_h[MTOT * Hh];        // GAT projections (fp32)
__device__ float g_spw[(size_t)MTOT * G4H];  // spatial @ W_ih0^T + bias (interleaved cols)
__device__ float g_c0[NTOT * Hh];
__device__ float g_c1[NTOT * Hh];
__device__ float g_h1f[NTOT * Hh];      // fp32 h1 for LayerNorm
__device__ float g_bsum0[G4H];          // interleaved
__device__ float g_bsum1[G4H];          // interleaved
__device__ float g_asrc[MTOT * NHEAD];
__device__ float g_adst[MTOT * NHEAD];
__device__ int   g_count[NTOT];
__device__ int   g_off[NTOT + 1];
__device__ int   g_cur[NTOT];
__device__ int   g_csr[EFULL];

// ============================ warp-MMA fp16x3 GEMM ============================
#define LDSROW   40
#define CHUNK_H  (128 * LDSROW)
#define CH2      (CHUNK_H * 2)
#define BUFB     (4 * CH2)

__device__ __forceinline__ uint32_t smem_u32(const void* p) {
    return (uint32_t)__cvta_generic_to_shared(p);
}
__device__ __forceinline__ void cp16(uint32_t dst, const void* src) {
    asm volatile("cp.async.ca.shared.global [%0], [%1], 16;" :: "r"(dst), "l"(src));
}
__device__ __forceinline__ void ldsm_x4(uint32_t (&r)[4], uint32_t addr) {
    asm volatile("ldmatrix.sync.aligned.m8n8.x4.shared.b16 {%0,%1,%2,%3}, [%4];"
                 : "=r"(r[0]), "=r"(r[1]), "=r"(r[2]), "=r"(r[3]) : "r"(addr));
}
__device__ __forceinline__ void mma16816(float (&c)[4], const uint32_t (&a)[4],
                                         uint32_t b0, uint32_t b1) {
    asm volatile("mma.sync.aligned.m16n8k16.row.col.f32.f16.f16.f32 "
                 "{%0,%1,%2,%3}, {%4,%5,%6,%7}, {%8,%9}, {%0,%1,%2,%3};"
                 : "+f"(c[0]), "+f"(c[1]), "+f"(c[2]), "+f"(c[3])
                 : "r"(a[0]), "r"(a[1]), "r"(a[2]), "r"(a[3]), "r"(b0), "r"(b1));
}
__device__ __forceinline__ void split_wr(__half* hi, __half* lo, size_t idx, float v) {
    __half h = __float2half_rn(v);
    hi[idx] = h;
    lo[idx] = __float2half_rn(v - __half2float(h));
}
__device__ __forceinline__ float sigmoidf(float x) { return 1.f / (1.f + __expf(-x)); }

// MODE 0: C = A@B^T (+A2@B2^T) (+bias) -> C
// MODE 1: LSTM gate epilogue on interleaved gate columns; updates cst, writes h (hi/lo[, hf])
template<int MODE>
__global__ __launch_bounds__(256) void gemm_wm(
    const __half* __restrict__ Ahi,  const __half* __restrict__ Alo,
    const __half* __restrict__ Bhi,  const __half* __restrict__ Blo,  int K,
    const __half* __restrict__ A2hi, const __half* __restrict__ A2lo,
    const __half* __restrict__ B2hi, const __half* __restrict__ B2lo, int K2,
    const float* __restrict__ bias, const float* __restrict__ Cadd,
    float* __restrict__ C, int ldC,
    float* __restrict__ cst, float* __restrict__ hf,
    __half* __restrict__ hhi, __half* __restrict__ hlo)
{
    extern __shared__ __half sbuf[];
    const uint32_t sb = smem_u32(sbuf);
    const int tid  = threadIdx.x;
    const int wid  = tid >> 5;
    const int lane = tid & 31;
    const int mBase   = blockIdx.y * 128;
    const int colBase = blockIdx.x * 128;
    const int warpM = (wid >> 2) * 64;
    const int warpN = (wid & 3) * 32;

    const int nc1 = K >> 5;
    const int nc2 = A2hi ? (K2 >> 5) : 0;
    const int nc  = nc1 + nc2;

    float acc[4][4][4];
#pragma unroll
    for (int i = 0; i < 4; i++)
#pragma unroll
        for (int j = 0; j < 4; j++)
#pragma unroll
            for (int q = 0; q < 4; q++) acc[i][j][q] = 0.f;

    auto issue = [&](int ci, int bsel) {
        int pair = (ci >= nc1) ? 1 : 0;
        int k0   = ((pair ? (ci - nc1) : ci) << 5);
        int Kp   = pair ? K2 : K;
        const __half* ah = pair ? A2hi : Ahi;
        const __half* al = pair ? A2lo : Alo;
        const __half* bh = pair ? B2hi : Bhi;
        const __half* bl = pair ? B2lo : Blo;
        uint32_t dB = sb + (uint32_t)bsel * BUFB;
#pragma unroll
        for (int j = 0; j < 2; j++) {
            int u = tid * 2 + j, row = u >> 2, seg = u & 3;
            uint32_t so = (uint32_t)((row * LDSROW + seg * 8) * 2);
            size_t aoff = (size_t)(mBase  + row) * Kp + k0 + seg * 8;
            size_t boff = (size_t)(colBase + row) * Kp + k0 + seg * 8;
            cp16(dB + 0 * CH2 + so, ah + aoff);
            cp16(dB + 1 * CH2 + so, al + aoff);
            cp16(dB + 2 * CH2 + so, bh + boff);
            cp16(dB + 3 * CH2 + so, bl + boff);
        }
        asm volatile("cp.async.commit_group;" ::: "memory");
    };

    issue(0, 0);
    for (int ci = 0; ci < nc; ci++) {
        int bsel = ci & 1;
        if (ci + 1 < nc) {
            issue(ci + 1, bsel ^ 1);
            asm volatile("cp.async.wait_group 1;" ::: "memory");
        } else {
            asm volatile("cp.async.wait_group 0;" ::: "memory");
        }
        __syncthreads();

        const uint32_t base = sb + (uint32_t)bsel * BUFB;
        const uint32_t aHiB = base,           aLoB = base + CH2;
        const uint32_t bHiB = base + 2 * CH2, bLoB = base + 3 * CH2;

#pragma unroll
        for (int ks = 0; ks < 2; ks++) {
            uint32_t ahi_f[4][4], alo_f[4][4], bhi_f[2][4], blo_f[2][4];
#pragma unroll
            for (int mi = 0; mi < 4; mi++) {
                uint32_t off = (uint32_t)(((warpM + mi * 16 + (lane & 15)) * LDSROW
                                           + ks * 16 + (lane >> 4) * 8) * 2);
                ldsm_x4(ahi_f[mi], aHiB + off);
                ldsm_x4(alo_f[mi], aLoB + off);
            }
#pragma unroll
            for (int p = 0; p < 2; p++) {
                uint32_t off = (uint32_t)(((warpN + p * 16 + (lane >> 4) * 8 + (lane & 7)) * LDSROW
                                           + ks * 16 + ((lane >> 3) & 1) * 8) * 2);
                ldsm_x4(bhi_f[p], bHiB + off);
                ldsm_x4(blo_f[p], bLoB + off);
            }
#pragma unroll
            for (int mi = 0; mi < 4; mi++)
#pragma unroll
                for (int p = 0; p < 2; p++)
#pragma unroll
                    for (int q = 0; q < 2; q++) {
                        int ni = p * 2 + q;
                        mma16816(acc[mi][ni], ahi_f[mi], bhi_f[p][q * 2], bhi_f[p][q * 2 + 1]);
                        mma16816(acc[mi][ni], ahi_f[mi], blo_f[p][q * 2], blo_f[p][q * 2 + 1]);
                        mma16816(acc[mi][ni], alo_f[mi], bhi_f[p][q * 2], bhi_f[p][q * 2 + 1]);
                    }
        }
        __syncthreads();
    }

    // ---- epilogue ----
    const int g = lane >> 2, t4 = lane & 3;
    if (MODE == 0) {
#pragma unroll
        for (int mi = 0; mi < 4; mi++) {
            int m0 = mBase + warpM + mi * 16 + g;
#pragma unroll
            for (int ni = 0; ni < 4; ni++) {
                int n = colBase + warpN + ni * 8 + t4 * 2;
                float b0 = 0.f, b1 = 0.f;
                if (bias) { b0 = bias[n]; b1 = bias[n + 1]; }
                float2 v0 = make_float2(acc[mi][ni][0] + b0, acc[mi][ni][1] + b1);
                float2 v1 = make_float2(acc[mi][ni][2] + b0, acc[mi][ni][3] + b1);
                *(float2*)(C + (size_t)m0 * ldC + n) = v0;
                *(float2*)(C + (size_t)(m0 + 8) * ldC + n) = v1;
            }
        }
    } else {
        // interleaved gate columns: col n -> dim d = n>>2, gate q = n&3 (i,f,g,o)
#pragma unroll
        for (int mi = 0; mi < 4; mi++) {
            int m0 = mBase + warpM + mi * 16 + g;
#pragma unroll
            for (int ni = 0; ni < 4; ni++) {
                int n = colBase + warpN + ni * 8 + t4 * 2;
                int d = n >> 2;
                float b0 = 0.f, b1 = 0.f;
                if (bias) { b0 = bias[n]; b1 = bias[n + 1]; }
                float4 mine;
                mine.x = acc[mi][ni][0] + b0;  // row m0,   col n
                mine.y = acc[mi][ni][1] + b1;  // row m0,   col n+1
                mine.z = acc[mi][ni][2] + b0;  // row m0+8, col n
                mine.w = acc[mi][ni][3] + b1;  // row m0+8, col n+1
                if (Cadd) {
                    float2 a0 = *(const float2*)(Cadd + (size_t)m0 * ldC + n);
                    float2 a1 = *(const float2*)(Cadd + (size_t)(m0 + 8) * ldC + n);
                    mine.x += a0.x; mine.y += a0.y; mine.z += a1.x; mine.w += a1.y;
                }
                float4 oth;
                oth.x = __shfl_xor_sync(0xffffffffu, mine.x, 1);
                oth.y = __shfl_xor_sync(0xffffffffu, mine.y, 1);
                oth.z = __shfl_xor_sync(0xffffffffu, mine.z, 1);
                oth.w = __shfl_xor_sync(0xffffffffu, mine.w, 1);
                bool evenp = (t4 & 1) == 0;
                float gi = evenp ? mine.x : oth.z;
                float gf = evenp ? mine.y : oth.w;
                float gg = evenp ? oth.x  : mine.z;
                float go = evenp ? oth.y  : mine.w;
                int row = evenp ? m0 : m0 + 8;
                size_t idx = (size_t)row * Hh + d;
                float cn = sigmoidf(gf) * cst[idx] + sigmoidf(gi) * tanhf(gg);
                cst[idx] = cn;
                float hv = sigmoidf(go) * tanhf(cn);
                if (hf) hf[idx] = hv;
                split_wr(hhi, hlo, idx, hv);
            }
        }
    }
}

// ---------------- small prep kernels ----------------
__global__ void transpose_x(const float* __restrict__ x) {
    int idx = blockIdx.x * blockDim.x + threadIdx.x;
    if (idx >= MTOT * Ff) return;
    int f  = idx & 63;
    int r  = idx >> 6;
    int n  = r & (Nn - 1);
    int bt = r >> 11;
    int b  = bt & 3;
    int t  = bt >> 2;
    float v = x[(((size_t)(b * Tt + t) * Nn + n) << 6) + f];
    split_wr(g_xhi, g_xlo, idx, v);
}

__global__ void wt_kernel(const float* __restrict__ W) {
    int i = blockIdx.x * blockDim.x + threadIdx.x;
    if (i >= Hh * Ff) return;
    int n = i >> 6, k = i & 63;
    split_wr(g_wthi, g_wtlo, i, W[k * Hh + n]);
}

// split + interleave LSTM weight rows: new row 4d+q = original row q*128+d
__global__ void split_w(const float* __restrict__ w0, const float* __restrict__ u0,
                        const float* __restrict__ w1, const float* __restrict__ u1) {
    int i = blockIdx.x * blockDim.x + threadIdx.x;
    if (i >= 4 * G4H * Hh) return;
    int which = i >> 16;
    int j = i & 65535;
    int orow = j >> 7, col = j & 127;
    int q = orow >> 7, d = orow & 127;
    int nj = ((d << 2) | q) * 128 + col;
    if      (which == 0) split_wr(g_w0hi, g_w0lo, nj, w0[j]);
    else if (which == 1) split_wr(g_u0hi, g_u0lo, nj, u0[j]);
    else if (which == 2) split_wr(g_w1hi, g_w1lo, nj, w1[j]);
    else                 split_wr(g_u1hi, g_u1lo, nj, u1[j]);
}

__global__ void init_kernel(const float* __restrict__ b_ih0, const float* __restrict__ b_hh0,
                            const float* __restrict__ b_ih1, const float* __restrict__ b_hh1) {
    int i = blockIdx.x * blockDim.x + threadIdx.x;
    if (i < NTOT) g_count[i] = 1;
    if (i < G4H) {
        int q = i >> 7, d = i & 127;
        int ni = (d << 2) | q;
        g_bsum0[ni] = b_ih0[i] + b_hh0[i];
        g_bsum1[ni] = b_ih1[i] + b_hh1[i];
    }
}

__global__ void zero_state() {
    int i = blockIdx.x * blockDim.x + threadIdx.x;
    if (i >= NTOT * Hh) return;
    g_c0[i] = 0.f; g_c1[i] = 0.f;
    __half z = __float2half(0.f);
    g_h0hi[i] = z; g_h0lo[i] = z; g_h1hi[i] = z; g_h1lo[i] = z;  // slot 0
}

__global__ void count_kernel(const int* __restrict__ ei) {
    int e = blockIdx.x * blockDim.x + threadIdx.x;
    if (e < Ee) atomicAdd(&g_count[ei[Ee + e]], 1);
}

__global__ void scan_kernel() {
    __shared__ int part[256];
    int tid  = threadIdx.x;
    int base = tid * 32;
    int local[32];
    int s = 0;
#pragma unroll
    for (int i = 0; i < 32; i++) { local[i] = g_count[base + i]; s += local[i]; }
    part[tid] = s;
    __syncthreads();
    for (int off = 1; off < 256; off <<= 1) {
        int v = (tid >= off) ? part[tid - off] : 0;
        __syncthreads();
        part[tid] += v;
        __syncthreads();
    }
    int run = part[tid] - s;
#pragma unroll
    for (int i = 0; i < 32; i++) {
        g_off[base + i] = run;
        g_cur[base + i] = run;
        run += local[i];
    }
    if (tid == 255) g_off[NTOT] = run;
}

__global__ void fill_kernel(const int* __restrict__ ei) {
    int e = blockIdx.x * blockDim.x + threadIdx.x;
    if (e < Ee) {
        int d = ei[Ee + e];
        int p = atomicAdd(&g_cur[d], 1);
        g_csr[p] = ei[e];
    } else if (e < EFULL) {
        int v = e - Ee;
        int p = atomicAdd(&g_cur[v], 1);
        g_csr[p] = v;
    }
}

// ---------------- per-head attention logits ----------------
__global__ void att_kernel(const float* __restrict__ att_src, const float* __restrict__ att_dst) {
    int gw   = (blockIdx.x * blockDim.x + threadIdx.x) >> 5;
    int lane = threadIdx.x & 31;
    if (gw >= MTOT) return;
    const float* hr = g_h + (size_t)gw * 128;
    float ps[4], pd[4];
#pragma unroll
    for (int j = 0; j < 4; j++) {
        float hv = hr[j * 32 + lane];
        ps[j] = hv * att_src[j * 32 + lane];
        pd[j] = hv * att_dst[j * 32 + lane];
    }
#pragma unroll
    for (int off = 16; off; off >>= 1)
#pragma unroll
        for (int j = 0; j < 4; j++) {
            ps[j] += __shfl_xor_sync(0xffffffffu, ps[j], off);
            pd[j] += __shfl_xor_sync(0xffffffffu, pd[j], off);
        }
    if (lane == 0)
#pragma unroll
        for (int j = 0; j < 4; j++) {
            g_asrc[gw * 4 + j] = ps[j];
            g_adst[gw * 4 + j] = pd[j];
        }
}

// ---------------- GAT edge softmax + aggregation (warp per (node,t)) ----------------
__global__ void gat_kernel(const float* __restrict__ gat_bias) {
    int warp = threadIdx.x >> 5;
    int lane = threadIdx.x & 31;
    int node = blockIdx.x * 8 + warp;
    int t    = blockIdx.y;
    int beg  = g_off[node], end = g_off[node + 1];

    float ad[4];
#pragma unroll
    for (int j = 0; j < 4; j++) ad[j] = g_adst[(t * NTOT + node) * 4 + j];

    float mx[4] = {-1e30f, -1e30f, -1e30f, -1e30f};
    for (int e = beg + lane; e < end; e += 32) {
        int s = g_csr[e];
        const float* as = g_asrc + (t * NTOT + s) * 4;
#pragma unroll
        for (int j = 0; j < 4; j++) {
            float v = as[j] + ad[j];
            v = v > 0.f ? v : 0.2f * v;
            mx[j] = fmaxf(mx[j], v);
        }
    }
#pragma unroll
    for (int off = 16; off; off >>= 1)
#pragma unroll
        for (int j = 0; j < 4; j++) mx[j] = fmaxf(mx[j], __shfl_xor_sync(0xffffffffu, mx[j], off));

    float den[4] = {0.f, 0.f, 0.f, 0.f};
    for (int e = beg + lane; e < end; e += 32) {
        int s = g_csr[e];
        const float* as = g_asrc + (t * NTOT + s) * 4;
#pragma unroll
        for (int j = 0; j < 4; j++) {
            float v = as[j] + ad[j];
            v = v > 0.f ? v : 0.2f * v;
            den[j] += __expf(v - mx[j]);
        }
    }
#pragma unroll
    for (int off = 16; off; off >>= 1)
#pragma unroll
        for (int j = 0; j < 4; j++) den[j] += __shfl_xor_sync(0xffffffffu, den[j], off);

    float rden[4];
#pragma unroll
    for (int j = 0; j < 4; j++) rden[j] = 1.f / den[j];

    float acc[4] = {0.f, 0.f, 0.f, 0.f};
    for (int e = beg; e < end; e++) {
        int s = g_csr[e];
        const float* as = g_asrc + (t * NTOT + s) * 4;
        const float* hs = g_h + (size_t)(t * NTOT + s) * 128;
#pragma unroll
        for (int j = 0; j < 4; j++) {
            float v = as[j] + ad[j];
            v = v > 0.f ? v : 0.2f * v;
            float w = __expf(v - mx[j]) * rden[j];
            acc[j] += w * hs[j * 32 + lane];
        }
    }
#pragma unroll
    for (int j = 0; j < 4; j++) {
        int d = j * 32 + lane;
        float r = fmaxf(acc[j] + gat_bias[d], 0.f);
        split_wr(g_sphi, g_splo, (size_t)(t * NTOT + node) * 128 + d, r);
    }
}

// ---------------- LayerNorm ----------------
__global__ void ln_kernel(const float* __restrict__ gamma, const float* __restrict__ beta,
                          float* __restrict__ out) {
    int gw   = (blockIdx.x * blockDim.x + threadIdx.x) >> 5;
    int lane = threadIdx.x & 31;
    if (gw >= NTOT) return;
    const float* hr = g_h1f + (size_t)gw * 128;
    float v[4];
    float s = 0.f, ss = 0.f;
#pragma unroll
    for (int j = 0; j < 4; j++) {
        v[j] = hr[j * 32 + lane];
        s += v[j];
        ss += v[j] * v[j];
    }
#pragma unroll
    for (int off = 16; off; off >>= 1) {
        s  += __shfl_xor_sync(0xffffffffu, s, off);
        ss += __shfl_xor_sync(0xffffffffu, ss, off);
    }
    float mu   = s * (1.f / 128.f);
    float var  = ss * (1.f / 128.f) - mu * mu;
    float rstd = rsqrtf(var + 1e-5f);
#pragma unroll
    for (int j = 0; j < 4; j++) {
        int d = j * 32 + lane;
        out[(size_t)gw * 128 + d] = (v[j] - mu) * rstd * gamma[d] + beta[d];
    }
}

// ---------------- launch ----------------
template <typename T>
static T* sym(const void* s) { void* p = nullptr; cudaGetSymbolAddress(&p, s); return (T*)p; }

extern "C" void kernel_launch(void* const* d_in, const int* in_sizes, int n_in,
                              void* d_out, int out_size) {
    const float* x        = (const float*)d_in[0];
    const float* W        = (const float*)d_in[1];
    const float* att_src  = (const float*)d_in[2];
    const float* att_dst  = (const float*)d_in[3];
    const float* gat_bias = (const float*)d_in[4];
    const float* W_ih0    = (const float*)d_in[5];
    const float* W_hh0    = (const float*)d_in[6];
    const float* b_ih0    = (const float*)d_in[7];
    const float* b_hh0    = (const float*)d_in[8];
    const float* W_ih1    = (const float*)d_in[9];
    const float* W_hh1    = (const float*)d_in[10];
    const float* b_ih1    = (const float*)d_in[11];
    const float* b_hh1    = (const float*)d_in[12];
    const float* ln_gamma = (const float*)d_in[13];
    const float* ln_beta  = (const float*)d_in[14];
    const int*   edge_index = (const int*)d_in[15];
    float* out = (float*)d_out;

    __half* p_xhi  = sym<__half>(g_xhi);  __half* p_xlo  = sym<__half>(g_xlo);
    __half* p_wthi = sym<__half>(g_wthi); __half* p_wtlo = sym<__half>(g_wtlo);
    __half* p_sphi = sym<__half>(g_sphi); __half* p_splo = sym<__half>(g_splo);
    __half* p_w0hi = sym<__half>(g_w0hi); __half* p_w0lo = sym<__half>(g_w0lo);
    __half* p_u0hi = sym<__half>(g_u0hi); __half* p_u0lo = sym<__half>(g_u0lo);
    __half* p_w1hi = sym<__half>(g_w1hi); __half* p_w1lo = sym<__half>(g_w1lo);
    __half* p_u1hi = sym<__half>(g_u1hi); __half* p_u1lo = sym<__half>(g_u1lo);
    __half* p_h0hi = sym<__half>(g_h0hi); __half* p_h0lo = sym<__half>(g_h0lo);
    __half* p_h1hi = sym<__half>(g_h1hi); __half* p_h1lo = sym<__half>(g_h1lo);
    float* p_h     = sym<float>(g_h);
    float* p_spw   = sym<float>(g_spw);
    float* p_c0    = sym<float>(g_c0);
    float* p_c1    = sym<float>(g_c1);
    float* p_h1f   = sym<float>(g_h1f);
    float* p_bsum0 = sym<float>(g_bsum0);
    float* p_bsum1 = sym<float>(g_bsum1);

    const int smemB = 2 * BUFB;   // 81920
    cudaFuncSetAttribute(gemm_wm<0>, cudaFuncAttributeMaxDynamicSharedMemorySize, smemB);
    cudaFuncSetAttribute(gemm_wm<1>, cudaFuncAttributeMaxDynamicSharedMemorySize, smemB);

    const size_t SLOT = (size_t)NTOT * Hh;

    // launches 1-5 (ncu -s 5 -c 1 captures launch #6 = projection GEMM)
    transpose_x<<<(MTOT * Ff + 255) / 256, 256>>>(x);
    wt_kernel<<<(Hh * Ff + 255) / 256, 256>>>(W);
    split_w<<<(4 * G4H * Hh + 255) / 256, 256>>>(W_ih0, W_hh0, W_ih1, W_hh1);
    init_kernel<<<(NTOT + 255) / 256, 256>>>(b_ih0, b_hh0, b_ih1, b_hh1);
    zero_state<<<(NTOT * Hh + 255) / 256, 256>>>();

    // launch 6: h = x_flat @ Wt^T  (M=81920, N=128, K=64)
    gemm_wm<0><<<dim3(1, MTOT / 128), 256, smemB>>>(
        p_xhi, p_xlo, p_wthi, p_wtlo, Ff,
        nullptr, nullptr, nullptr, nullptr, 0,
        nullptr, nullptr, p_h, Hh, nullptr, nullptr, nullptr, nullptr);

    count_kernel<<<(Ee + 255) / 256, 256>>>(edge_index);
    scan_kernel<<<1, 256>>>();
    fill_kernel<<<(EFULL + 255) / 256, 256>>>(edge_index);
    att_kernel<<<(MTOT * 32 + 255) / 256, 256>>>(att_src, att_dst);
    gat_kernel<<<dim3(NTOT / 8, Tt), 256>>>(gat_bias);

    // hoisted layer-0 input gates for all t: spw = spatial @ W_ih0^T + bsum0 (interleaved)
    gemm_wm<0><<<dim3(4, MTOT / 128), 256, smemB>>>(
        p_sphi, p_splo, p_w0hi, p_w0lo, Hh,
        nullptr, nullptr, nullptr, nullptr, 0,
        p_bsum0, nullptr, p_spw, G4H, nullptr, nullptr, nullptr, nullptr);

    for (int t = 0; t < Tt; t++) {
        // layer 0: gates = spw[t] + h0[t] @ U0^T  -> h0[t+1], c0
        gemm_wm<1><<<dim3(4, NTOT / 128), 256, smemB>>>(
            p_h0hi + (size_t)t * SLOT, p_h0lo + (size_t)t * SLOT, p_u0hi, p_u0lo, Hh,
            nullptr, nullptr, nullptr, nullptr, 0,
            nullptr, p_spw + (size_t)t * NTOT * G4H, nullptr, G4H,
            p_c0, nullptr, p_h0hi + (size_t)(t + 1) * SLOT, p_h0lo + (size_t)(t + 1) * SLOT);
        // layer 1: gates = h0[t+1] @ W1^T + h1[t] @ U1^T + bsum1 -> h1[t+1], c1, h1f
        gemm_wm<1><<<dim3(4, NTOT / 128), 256, smemB>>>(
            p_h0hi + (size_t)(t + 1) * SLOT, p_h0lo + (size_t)(t + 1) * SLOT, p_w1hi, p_w1lo, Hh,
            p_h1hi + (size_t)t * SLOT, p_h1lo + (size_t)t * SLOT, p_u1hi, p_u1lo, Hh,
            p_bsum1, nullptr, nullptr, G4H,
            p_c1, p_h1f, p_h1hi + (size_t)(t + 1) * SLOT, p_h1lo + (size_t)(t + 1) * SLOT);
    }

    ln_kernel<<<(NTOT * 32 + 255) / 256, 256>>>(ln_gamma, ln_beta, out);
}

// round 11
// speedup vs baseline: 1.0390x; 1.0390x over previous
#include <cuda_runtime.h>
#include <cuda_fp16.h>
#include <math.h>
#include <stdint.h>

#define Bb    4
#define Tt    10
#define Nn    2048
#define Ff    64
#define Hh    128
#define NHEAD 4
#define Dd    32
#define Ee    65536
#define NTOT  8192            // B*N
#define MTOT  81920           // T*NTOT
#define G4H   512             // 4*H
#define EFULL (Ee + NTOT)     // edges + self loops

// ---------------- device scratch (no allocations allowed) ----------------
__device__ __align__(16) __half g_xhi[MTOT * Ff],  g_xlo[MTOT * Ff];
__device__ __align__(16) __half g_wthi[Hh * Ff],   g_wtlo[Hh * Ff];
__device__ __align__(16) __half g_sphi[MTOT * Hh], g_splo[MTOT * Hh];
// LSTM weights, rows interleaved: new row 4d+q = original row q*128+d
__device__ __align__(16) __half g_w0hi[G4H * Hh],  g_w0lo[G4H * Hh];   // W_ih0
__device__ __align__(16) __half g_u0hi[G4H * Hh],  g_u0lo[G4H * Hh];   // W_hh0
__device__ __align__(16) __half g_w1hi[G4H * Hh],  g_w1lo[G4H * Hh];   // W_ih1
__device__ __align__(16) __half g_u1hi[G4H * Hh],  g_u1lo[G4H * Hh];   // W_hh1
// time-ringed recurrent state (slot t read, slot t+1 written)
__device__ __align__(16) __half g_h0hi[(Tt + 1) * NTOT * Hh], g_h0lo[(Tt + 1) * NTOT * Hh];
__device__ __align__(16) __half g_h1hi[(Tt + 1) * NTOT * Hh], g_h1lo[(Tt + 1) * NTOT * Hh];

__device__ float g_h[MTOT * Hh];        // GAT projections (fp32)
__device__ float g_c0[NTOT * Hh];
__device__ float g_c1[NTOT * Hh];
__device__ float g_h1f[NTOT * Hh];      // fp32 h1 for LayerNorm
__device__ float g_bsum0[G4H];          // interleaved
__device__ float g_bsum1[G4H];          // interleaved
__device__ float g_asrc[MTOT * NHEAD];
__device__ float g_adst[MTOT * NHEAD];
__device__ int   g_count[NTOT];
__device__ int   g_off[NTOT + 1];
__device__ int   g_cur[NTOT];
__device__ int   g_csr[EFULL];

// ============================ warp-MMA fp16x3 GEMM ============================
#define LDSROW   40
#define CHUNK_H  (128 * LDSROW)
#define CH2      (CHUNK_H * 2)
#define BUFB     (4 * CH2)

__device__ __forceinline__ uint32_t smem_u32(const void* p) {
    return (uint32_t)__cvta_generic_to_shared(p);
}
__device__ __forceinline__ void cp16(uint32_t dst, const void* src) {
    asm volatile("cp.async.ca.shared.global [%0], [%1], 16;" :: "r"(dst), "l"(src));
}
__device__ __forceinline__ void ldsm_x4(uint32_t (&r)[4], uint32_t addr) {
    asm volatile("ldmatrix.sync.aligned.m8n8.x4.shared.b16 {%0,%1,%2,%3}, [%4];"
                 : "=r"(r[0]), "=r"(r[1]), "=r"(r[2]), "=r"(r[3]) : "r"(addr));
}
__device__ __forceinline__ void mma16816(float (&c)[4], const uint32_t (&a)[4],
                                         uint32_t b0, uint32_t b1) {
    asm volatile("mma.sync.aligned.m16n8k16.row.col.f32.f16.f16.f32 "
                 "{%0,%1,%2,%3}, {%4,%5,%6,%7}, {%8,%9}, {%0,%1,%2,%3};"
                 : "+f"(c[0]), "+f"(c[1]), "+f"(c[2]), "+f"(c[3])
                 : "r"(a[0]), "r"(a[1]), "r"(a[2]), "r"(a[3]), "r"(b0), "r"(b1));
}
__device__ __forceinline__ void split_wr(__half* hi, __half* lo, size_t idx, float v) {
    __half h = __float2half_rn(v);
    hi[idx] = h;
    lo[idx] = __float2half_rn(v - __half2float(h));
}
__device__ __forceinline__ float sigmoidf(float x) { return 1.f / (1.f + __expf(-x)); }

// MODE 0: C = A@B^T (+A2@B2^T) (+bias) -> C
// MODE 1: LSTM gate epilogue on interleaved gate columns; updates cst, writes h (hi/lo[, hf])
template<int MODE>
__global__ __launch_bounds__(256) void gemm_wm(
    const __half* __restrict__ Ahi,  const __half* __restrict__ Alo,
    const __half* __restrict__ Bhi,  const __half* __restrict__ Blo,  int K,
    const __half* __restrict__ A2hi, const __half* __restrict__ A2lo,
    const __half* __restrict__ B2hi, const __half* __restrict__ B2lo, int K2,
    const float* __restrict__ bias,
    float* __restrict__ C, int ldC,
    float* __restrict__ cst, float* __restrict__ hf,
    __half* __restrict__ hhi, __half* __restrict__ hlo)
{
    extern __shared__ __half sbuf[];
    const uint32_t sb = smem_u32(sbuf);
    const int tid  = threadIdx.x;
    const int wid  = tid >> 5;
    const int lane = tid & 31;
    const int mBase   = blockIdx.y * 128;
    const int colBase = blockIdx.x * 128;
    const int warpM = (wid >> 2) * 64;
    const int warpN = (wid & 3) * 32;

    const int nc1 = K >> 5;
    const int nc2 = A2hi ? (K2 >> 5) : 0;
    const int nc  = nc1 + nc2;

    float acc[4][4][4];
#pragma unroll
    for (int i = 0; i < 4; i++)
#pragma unroll
        for (int j = 0; j < 4; j++)
#pragma unroll
            for (int q = 0; q < 4; q++) acc[i][j][q] = 0.f;

    auto issue = [&](int ci, int bsel) {
        int pair = (ci >= nc1) ? 1 : 0;
        int k0   = ((pair ? (ci - nc1) : ci) << 5);
        int Kp   = pair ? K2 : K;
        const __half* ah = pair ? A2hi : Ahi;
        const __half* al = pair ? A2lo : Alo;
        const __half* bh = pair ? B2hi : Bhi;
        const __half* bl = pair ? B2lo : Blo;
        uint32_t dB = sb + (uint32_t)bsel * BUFB;
#pragma unroll
        for (int j = 0; j < 2; j++) {
            int u = tid * 2 + j, row = u >> 2, seg = u & 3;
            uint32_t so = (uint32_t)((row * LDSROW + seg * 8) * 2);
            size_t aoff = (size_t)(mBase  + row) * Kp + k0 + seg * 8;
            size_t boff = (size_t)(colBase + row) * Kp + k0 + seg * 8;
            cp16(dB + 0 * CH2 + so, ah + aoff);
            cp16(dB + 1 * CH2 + so, al + aoff);
            cp16(dB + 2 * CH2 + so, bh + boff);
            cp16(dB + 3 * CH2 + so, bl + boff);
        }
        asm volatile("cp.async.commit_group;" ::: "memory");
    };

    issue(0, 0);
    for (int ci = 0; ci < nc; ci++) {
        int bsel = ci & 1;
        if (ci + 1 < nc) {
            issue(ci + 1, bsel ^ 1);
            asm volatile("cp.async.wait_group 1;" ::: "memory");
        } else {
            asm volatile("cp.async.wait_group 0;" ::: "memory");
        }
        __syncthreads();

        const uint32_t base = sb + (uint32_t)bsel * BUFB;
        const uint32_t aHiB = base,           aLoB = base + CH2;
        const uint32_t bHiB = base + 2 * CH2, bLoB = base + 3 * CH2;

#pragma unroll
        for (int ks = 0; ks < 2; ks++) {
            uint32_t ahi_f[4][4], alo_f[4][4], bhi_f[2][4], blo_f[2][4];
#pragma unroll
            for (int mi = 0; mi < 4; mi++) {
                uint32_t off = (uint32_t)(((warpM + mi * 16 + (lane & 15)) * LDSROW
                                           + ks * 16 + (lane >> 4) * 8) * 2);
                ldsm_x4(ahi_f[mi], aHiB + off);
                ldsm_x4(alo_f[mi], aLoB + off);
            }
#pragma unroll
            for (int p = 0; p < 2; p++) {
                uint32_t off = (uint32_t)(((warpN + p * 16 + (lane >> 4) * 8 + (lane & 7)) * LDSROW
                                           + ks * 16 + ((lane >> 3) & 1) * 8) * 2);
                ldsm_x4(bhi_f[p], bHiB + off);
                ldsm_x4(blo_f[p], bLoB + off);
            }
#pragma unroll
            for (int mi = 0; mi < 4; mi++)
#pragma unroll
                for (int p = 0; p < 2; p++)
#pragma unroll
                    for (int q = 0; q < 2; q++) {
                        int ni = p * 2 + q;
                        mma16816(acc[mi][ni], ahi_f[mi], bhi_f[p][q * 2], bhi_f[p][q * 2 + 1]);
                        mma16816(acc[mi][ni], ahi_f[mi], blo_f[p][q * 2], blo_f[p][q * 2 + 1]);
                        mma16816(acc[mi][ni], alo_f[mi], bhi_f[p][q * 2], bhi_f[p][q * 2 + 1]);
                    }
        }
        __syncthreads();
    }

    // ---- epilogue ----
    const int g = lane >> 2, t4 = lane & 3;
    if (MODE == 0) {
#pragma unroll
        for (int mi = 0; mi < 4; mi++) {
            int m0 = mBase + warpM + mi * 16 + g;
#pragma unroll
            for (int ni = 0; ni < 4; ni++) {
                int n = colBase + warpN + ni * 8 + t4 * 2;
                float b0 = 0.f, b1 = 0.f;
                if (bias) { b0 = bias[n]; b1 = bias[n + 1]; }
                float2 v0 = make_float2(acc[mi][ni][0] + b0, acc[mi][ni][1] + b1);
                float2 v1 = make_float2(acc[mi][ni][2] + b0, acc[mi][ni][3] + b1);
                *(float2*)(C + (size_t)m0 * ldC + n) = v0;
                *(float2*)(C + (size_t)(m0 + 8) * ldC + n) = v1;
            }
        }
    } else {
        // interleaved gate columns: col n -> dim d = n>>2, gate q = n&3 (i,f,g,o)
#pragma unroll
        for (int mi = 0; mi < 4; mi++) {
            int m0 = mBase + warpM + mi * 16 + g;
#pragma unroll
            for (int ni = 0; ni < 4; ni++) {
                int n = colBase + warpN + ni * 8 + t4 * 2;
                int d = n >> 2;
                float b0 = bias[n], b1 = bias[n + 1];
                float4 mine;
                mine.x = acc[mi][ni][0] + b0;  // row m0,   col n
                mine.y = acc[mi][ni][1] + b1;  // row m0,   col n+1
                mine.z = acc[mi][ni][2] + b0;  // row m0+8, col n
                mine.w = acc[mi][ni][3] + b1;  // row m0+8, col n+1
                float4 oth;
                oth.x = __shfl_xor_sync(0xffffffffu, mine.x, 1);
                oth.y = __shfl_xor_sync(0xffffffffu, mine.y, 1);
                oth.z = __shfl_xor_sync(0xffffffffu, mine.z, 1);
                oth.w = __shfl_xor_sync(0xffffffffu, mine.w, 1);
                bool evenp = (t4 & 1) == 0;
                float gi = evenp ? mine.x : oth.z;
                float gf = evenp ? mine.y : oth.w;
                float gg = evenp ? oth.x  : mine.z;
                float go = evenp ? oth.y  : mine.w;
                int row = evenp ? m0 : m0 + 8;
                size_t idx = (size_t)row * Hh + d;
                float cn = sigmoidf(gf) * cst[idx] + sigmoidf(gi) * tanhf(gg);
                cst[idx] = cn;
                float hv = sigmoidf(go) * tanhf(cn);
                if (hf) hf[idx] = hv;
                split_wr(hhi, hlo, idx, hv);
            }
        }
    }
}

// ---------------- small prep kernels ----------------
__global__ void transpose_x(const float* __restrict__ x) {
    int idx = blockIdx.x * blockDim.x + threadIdx.x;
    if (idx >= MTOT * Ff) return;
    int f  = idx & 63;
    int r  = idx >> 6;
    int n  = r & (Nn - 1);
    int bt = r >> 11;
    int b  = bt & 3;
    int t  = bt >> 2;
    float v = x[(((size_t)(b * Tt + t) * Nn + n) << 6) + f];
    split_wr(g_xhi, g_xlo, idx, v);
}

__global__ void wt_kernel(const float* __restrict__ W) {
    int i = blockIdx.x * blockDim.x + threadIdx.x;
    if (i >= Hh * Ff) return;
    int n = i >> 6, k = i & 63;
    split_wr(g_wthi, g_wtlo, i, W[k * Hh + n]);
}

// split + interleave LSTM weight rows: new row 4d+q = original row q*128+d
__global__ void split_w(const float* __restrict__ w0, const float* __restrict__ u0,
                        const float* __restrict__ w1, const float* __restrict__ u1) {
    int i = blockIdx.x * blockDim.x + threadIdx.x;
    if (i >= 4 * G4H * Hh) return;
    int which = i >> 16;
    int j = i & 65535;
    int orow = j >> 7, col = j & 127;
    int q = orow >> 7, d = orow & 127;
    int nj = ((d << 2) | q) * 128 + col;
    if      (which == 0) split_wr(g_w0hi, g_w0lo, nj, w0[j]);
    else if (which == 1) split_wr(g_u0hi, g_u0lo, nj, u0[j]);
    else if (which == 2) split_wr(g_w1hi, g_w1lo, nj, w1[j]);
    else                 split_wr(g_u1hi, g_u1lo, nj, u1[j]);
}

__global__ void init_kernel(const float* __restrict__ b_ih0, const float* __restrict__ b_hh0,
                            const float* __restrict__ b_ih1, const float* __restrict__ b_hh1) {
    int i = blockIdx.x * blockDim.x + threadIdx.x;
    if (i < NTOT) g_count[i] = 1;
    if (i < G4H) {
        int q = i >> 7, d = i & 127;
        int ni = (d << 2) | q;
        g_bsum0[ni] = b_ih0[i] + b_hh0[i];
        g_bsum1[ni] = b_ih1[i] + b_hh1[i];
    }
}

__global__ void zero_state() {
    int i = blockIdx.x * blockDim.x + threadIdx.x;
    if (i >= NTOT * Hh) return;
    g_c0[i] = 0.f; g_c1[i] = 0.f;
    __half z = __float2half(0.f);
    g_h0hi[i] = z; g_h0lo[i] = z; g_h1hi[i] = z; g_h1lo[i] = z;  // slot 0
}

__global__ void count_kernel(const int* __restrict__ ei) {
    int e = blockIdx.x * blockDim.x + threadIdx.x;
    if (e < Ee) atomicAdd(&g_count[ei[Ee + e]], 1);
}

__global__ void scan_kernel() {
    __shared__ int part[256];
    int tid  = threadIdx.x;
    int base = tid * 32;
    int local[32];
    int s = 0;
#pragma unroll
    for (int i = 0; i < 32; i++) { local[i] = g_count[base + i]; s += local[i]; }
    part[tid] = s;
    __syncthreads();
    for (int off = 1; off < 256; off <<= 1) {
        int v = (tid >= off) ? part[tid - off] : 0;
        __syncthreads();
        part[tid] += v;
        __syncthreads();
    }
    int run = part[tid] - s;
#pragma unroll
    for (int i = 0; i < 32; i++) {
        g_off[base + i] = run;
        g_cur[base + i] = run;
        run += local[i];
    }
    if (tid == 255) g_off[NTOT] = run;
}

__global__ void fill_kernel(const int* __restrict__ ei) {
    int e = blockIdx.x * blockDim.x + threadIdx.x;
    if (e < Ee) {
        int d = ei[Ee + e];
        int p = atomicAdd(&g_cur[d], 1);
        g_csr[p] = ei[e];
    } else if (e < EFULL) {
        int v = e - Ee;
        int p = atomicAdd(&g_cur[v], 1);
        g_csr[p] = v;
    }
}

// ---------------- per-head attention logits ----------------
__global__ void att_kernel(const float* __restrict__ att_src, const float* __restrict__ att_dst) {
    int gw   = (blockIdx.x * blockDim.x + threadIdx.x) >> 5;
    int lane = threadIdx.x & 31;
    if (gw >= MTOT) return;
    const float* hr = g_h + (size_t)gw * 128;
    float ps[4], pd[4];
#pragma unroll
    for (int j = 0; j < 4; j++) {
        float hv = hr[j * 32 + lane];
        ps[j] = hv * att_src[j * 32 + lane];
        pd[j] = hv * att_dst[j * 32 + lane];
    }
#pragma unroll
    for (int off = 16; off; off >>= 1)
#pragma unroll
        for (int j = 0; j < 4; j++) {
            ps[j] += __shfl_xor_sync(0xffffffffu, ps[j], off);
            pd[j] += __shfl_xor_sync(0xffffffffu, pd[j], off);
        }
    if (lane == 0)
#pragma unroll
        for (int j = 0; j < 4; j++) {
            g_asrc[gw * 4 + j] = ps[j];
            g_adst[gw * 4 + j] = pd[j];
        }
}

// ---------------- GAT edge softmax + aggregation (warp per (node,t)) ----------------
__global__ void gat_kernel(const float* __restrict__ gat_bias) {
    int warp = threadIdx.x >> 5;
    int lane = threadIdx.x & 31;
    int node = blockIdx.x * 8 + warp;
    int t    = blockIdx.y;
    int beg  = g_off[node], end = g_off[node + 1];

    float ad[4];
#pragma unroll
    for (int j = 0; j < 4; j++) ad[j] = g_adst[(t * NTOT + node) * 4 + j];

    float mx[4] = {-1e30f, -1e30f, -1e30f, -1e30f};
    for (int e = beg + lane; e < end; e += 32) {
        int s = g_csr[e];
        const float* as = g_asrc + (t * NTOT + s) * 4;
#pragma unroll
        for (int j = 0; j < 4; j++) {
            float v = as[j] + ad[j];
            v = v > 0.f ? v : 0.2f * v;
            mx[j] = fmaxf(mx[j], v);
        }
    }
#pragma unroll
    for (int off = 16; off; off >>= 1)
#pragma unroll
        for (int j = 0; j < 4; j++) mx[j] = fmaxf(mx[j], __shfl_xor_sync(0xffffffffu, mx[j], off));

    float den[4] = {0.f, 0.f, 0.f, 0.f};
    for (int e = beg + lane; e < end; e += 32) {
        int s = g_csr[e];
        const float* as = g_asrc + (t * NTOT + s) * 4;
#pragma unroll
        for (int j = 0; j < 4; j++) {
            float v = as[j] + ad[j];
            v = v > 0.f ? v : 0.2f * v;
            den[j] += __expf(v - mx[j]);
        }
    }
#pragma unroll
    for (int off = 16; off; off >>= 1)
#pragma unroll
        for (int j = 0; j < 4; j++) den[j] += __shfl_xor_sync(0xffffffffu, den[j], off);

    float rden[4];
#pragma unroll
    for (int j = 0; j < 4; j++) rden[j] = 1.f / den[j];

    float acc[4] = {0.f, 0.f, 0.f, 0.f};
    for (int e = beg; e < end; e++) {
        int s = g_csr[e];
        const float* as = g_asrc + (t * NTOT + s) * 4;
        const float* hs = g_h + (size_t)(t * NTOT + s) * 128;
#pragma unroll
        for (int j = 0; j < 4; j++) {
            float v = as[j] + ad[j];
            v = v > 0.f ? v : 0.2f * v;
            float w = __expf(v - mx[j]) * rden[j];
            acc[j] += w * hs[j * 32 + lane];
        }
    }
#pragma unroll
    for (int j = 0; j < 4; j++) {
        int d = j * 32 + lane;
        float r = fmaxf(acc[j] + gat_bias[d], 0.f);
        split_wr(g_sphi, g_splo, (size_t)(t * NTOT + node) * 128 + d, r);
    }
}

// ---------------- LayerNorm ----------------
__global__ void ln_kernel(const float* __restrict__ gamma, const float* __restrict__ beta,
                          float* __restrict__ out) {
    int gw   = (blockIdx.x * blockDim.x + threadIdx.x) >> 5;
    int lane = threadIdx.x & 31;
    if (gw >= NTOT) return;
    const float* hr = g_h1f + (size_t)gw * 128;
    float v[4];
    float s = 0.f, ss = 0.f;
#pragma unroll
    for (int j = 0; j < 4; j++) {
        v[j] = hr[j * 32 + lane];
        s += v[j];
        ss += v[j] * v[j];
    }
#pragma unroll
    for (int off = 16; off; off >>= 1) {
        s  += __shfl_xor_sync(0xffffffffu, s, off);
        ss += __shfl_xor_sync(0xffffffffu, ss, off);
    }
    float mu   = s * (1.f / 128.f);
    float var  = ss * (1.f / 128.f) - mu * mu;
    float rstd = rsqrtf(var + 1e-5f);
#pragma unroll
    for (int j = 0; j < 4; j++) {
        int d = j * 32 + lane;
        out[(size_t)gw * 128 + d] = (v[j] - mu) * rstd * gamma[d] + beta[d];
    }
}

// ---------------- launch ----------------
template <typename T>
static T* sym(const void* s) { void* p = nullptr; cudaGetSymbolAddress(&p, s); return (T*)p; }

extern "C" void kernel_launch(void* const* d_in, const int* in_sizes, int n_in,
                              void* d_out, int out_size) {
    const float* x        = (const float*)d_in[0];
    const float* W        = (const float*)d_in[1];
    const float* att_src  = (const float*)d_in[2];
    const float* att_dst  = (const float*)d_in[3];
    const float* gat_bias = (const float*)d_in[4];
    const float* W_ih0    = (const float*)d_in[5];
    const float* W_hh0    = (const float*)d_in[6];
    const float* b_ih0    = (const float*)d_in[7];
    const float* b_hh0    = (const float*)d_in[8];
    const float* W_ih1    = (const float*)d_in[9];
    const float* W_hh1    = (const float*)d_in[10];
    const float* b_ih1    = (const float*)d_in[11];
    const float* b_hh1    = (const float*)d_in[12];
    const float* ln_gamma = (const float*)d_in[13];
    const float* ln_beta  = (const float*)d_in[14];
    const int*   edge_index = (const int*)d_in[15];
    float* out = (float*)d_out;

    __half* p_xhi  = sym<__half>(g_xhi);  __half* p_xlo  = sym<__half>(g_xlo);
    __half* p_wthi = sym<__half>(g_wthi); __half* p_wtlo = sym<__half>(g_wtlo);
    __half* p_sphi = sym<__half>(g_sphi); __half* p_splo = sym<__half>(g_splo);
    __half* p_w0hi = sym<__half>(g_w0hi); __half* p_w0lo = sym<__half>(g_w0lo);
    __half* p_u0hi = sym<__half>(g_u0hi); __half* p_u0lo = sym<__half>(g_u0lo);
    __half* p_w1hi = sym<__half>(g_w1hi); __half* p_w1lo = sym<__half>(g_w1lo);
    __half* p_u1hi = sym<__half>(g_u1hi); __half* p_u1lo = sym<__half>(g_u1lo);
    __half* p_h0hi = sym<__half>(g_h0hi); __half* p_h0lo = sym<__half>(g_h0lo);
    __half* p_h1hi = sym<__half>(g_h1hi); __half* p_h1lo = sym<__half>(g_h1lo);
    float* p_h     = sym<float>(g_h);
    float* p_c0    = sym<float>(g_c0);
    float* p_c1    = sym<float>(g_c1);
    float* p_h1f   = sym<float>(g_h1f);
    float* p_bsum0 = sym<float>(g_bsum0);
    float* p_bsum1 = sym<float>(g_bsum1);

    const int smemB = 2 * BUFB;   // 81920
    cudaFuncSetAttribute(gemm_wm<0>, cudaFuncAttributeMaxDynamicSharedMemorySize, smemB);
    cudaFuncSetAttribute(gemm_wm<1>, cudaFuncAttributeMaxDynamicSharedMemorySize, smemB);

    const size_t SLOT = (size_t)NTOT * Hh;

    // launches 1-5 (ncu -s 5 -c 1 captures launch #6 = projection GEMM)
    transpose_x<<<(MTOT * Ff + 255) / 256, 256>>>(x);
    wt_kernel<<<(Hh * Ff + 255) / 256, 256>>>(W);
    split_w<<<(4 * G4H * Hh + 255) / 256, 256>>>(W_ih0, W_hh0, W_ih1, W_hh1);
    init_kernel<<<(NTOT + 255) / 256, 256>>>(b_ih0, b_hh0, b_ih1, b_hh1);
    zero_state<<<(NTOT * Hh + 255) / 256, 256>>>();

    // launch 6: h = x_flat @ Wt^T  (M=81920, N=128, K=64)
    gemm_wm<0><<<dim3(1, MTOT / 128), 256, smemB>>>(
        p_xhi, p_xlo, p_wthi, p_wtlo, Ff,
        nullptr, nullptr, nullptr, nullptr, 0,
        nullptr, p_h, Hh, nullptr, nullptr, nullptr, nullptr);

    count_kernel<<<(Ee + 255) / 256, 256>>>(edge_index);
    scan_kernel<<<1, 256>>>();
    fill_kernel<<<(EFULL + 255) / 256, 256>>>(edge_index);
    att_kernel<<<(MTOT * 32 + 255) / 256, 256>>>(att_src, att_dst);
    gat_kernel<<<dim3(NTOT / 8, Tt), 256>>>(gat_bias);

    for (int t = 0; t < Tt; t++) {
        // layer 0: gates = spatial[t]@W0^T + h0[t]@U0^T + bsum0 -> fused -> h0[t+1], c0
        gemm_wm<1><<<dim3(4, NTOT / 128), 256, smemB>>>(
            p_sphi + (size_t)t * SLOT, p_splo + (size_t)t * SLOT, p_w0hi, p_w0lo, Hh,
            p_h0hi + (size_t)t * SLOT, p_h0lo + (size_t)t * SLOT, p_u0hi, p_u0lo, Hh,
            p_bsum0, nullptr, G4H,
            p_c0, nullptr, p_h0hi + (size_t)(t + 1) * SLOT, p_h0lo + (size_t)(t + 1) * SLOT);
        // layer 1: gates = h0[t+1]@W1^T + h1[t]@U1^T + bsum1 -> fused -> h1[t+1], c1, h1f
        gemm_wm<1><<<dim3(4, NTOT / 128), 256, smemB>>>(
            p_h0hi + (size_t)(t + 1) * SLOT, p_h0lo + (size_t)(t + 1) * SLOT, p_w1hi, p_w1lo, Hh,
            p_h1hi + (size_t)t * SLOT, p_h1lo + (size_t)t * SLOT, p_u1hi, p_u1lo, Hh,
            p_bsum1, nullptr, G4H,
            p_c1, p_h1f, p_h1hi + (size_t)(t + 1) * SLOT, p_h1lo + (size_t)(t + 1) * SLOT);
    }

    ln_kernel<<<(NTOT * 32 + 255) / 256, 256>>>(ln_gamma, ln_beta, out);
}

// round 14
// speedup vs baseline: 1.0441x; 1.0049x over previous
#include <cuda_runtime.h>
#include <cuda_fp16.h>
#include <math.h>
#include <stdint.h>

#define Bb    4
#define Tt    10
#define Nn    2048
#define Ff    64
#define Hh    128
#define NHEAD 4
#define Dd    32
#define Ee    65536
#define NTOT  8192            // B*N
#define MTOT  81920           // T*NTOT
#define G4H   512             // 4*H
#define EFULL (Ee + NTOT)     // edges + self loops

// ---------------- device scratch (no allocations allowed) ----------------
__device__ __align__(16) __half g_xhi[MTOT * Ff],  g_xlo[MTOT * Ff];
__device__ __align__(16) __half g_wthi[Hh * Ff],   g_wtlo[Hh * Ff];
__device__ __align__(16) __half g_sphi[MTOT * Hh], g_splo[MTOT * Hh];
// LSTM weights, rows interleaved: new row 4d+q = original row q*128+d
__device__ __align__(16) __half g_w0hi[G4H * Hh],  g_w0lo[G4H * Hh];   // W_ih0
__device__ __align__(16) __half g_u0hi[G4H * Hh],  g_u0lo[G4H * Hh];   // W_hh0
__device__ __align__(16) __half g_w1hi[G4H * Hh],  g_w1lo[G4H * Hh];   // W_ih1
__device__ __align__(16) __half g_u1hi[G4H * Hh],  g_u1lo[G4H * Hh];   // W_hh1
// time-ringed recurrent state (slot t read, slot t+1 written)
__device__ __align__(16) __half g_h0hi[(Tt + 1) * NTOT * Hh], g_h0lo[(Tt + 1) * NTOT * Hh];
__device__ __align__(16) __half g_h1hi[(Tt + 1) * NTOT * Hh], g_h1lo[(Tt + 1) * NTOT * Hh];

__device__ float g_h[MTOT * Hh];        // GAT projections (fp32)
__device__ float g_c0[NTOT * Hh];
__device__ float g_c1[NTOT * Hh];
__device__ float g_h1f[NTOT * Hh];      // fp32 h1 for LayerNorm
__device__ float g_bsum0[G4H];          // interleaved
__device__ float g_bsum1[G4H];          // interleaved
__device__ float g_asrc[MTOT * NHEAD];
__device__ float g_adst[MTOT * NHEAD];
__device__ int   g_count[NTOT];
__device__ int   g_off[NTOT + 1];
__device__ int   g_cur[NTOT];
__device__ int   g_csr[EFULL];

// ============================ warp-MMA fp16x3 GEMM ============================
#define LDSROW   40
#define CHUNK_H  (128 * LDSROW)
#define CH2      (CHUNK_H * 2)
#define BUFB     (4 * CH2)

__device__ __forceinline__ uint32_t smem_u32(const void* p) {
    return (uint32_t)__cvta_generic_to_shared(p);
}
__device__ __forceinline__ void cp16(uint32_t dst, const void* src) {
    asm volatile("cp.async.ca.shared.global [%0], [%1], 16;" :: "r"(dst), "l"(src));
}
__device__ __forceinline__ void ldsm_x4(uint32_t (&r)[4], uint32_t addr) {
    asm volatile("ldmatrix.sync.aligned.m8n8.x4.shared.b16 {%0,%1,%2,%3}, [%4];"
                 : "=r"(r[0]), "=r"(r[1]), "=r"(r[2]), "=r"(r[3]) : "r"(addr));
}
__device__ __forceinline__ void mma16816(float (&c)[4], const uint32_t (&a)[4],
                                         uint32_t b0, uint32_t b1) {
    asm volatile("mma.sync.aligned.m16n8k16.row.col.f32.f16.f16.f32 "
                 "{%0,%1,%2,%3}, {%4,%5,%6,%7}, {%8,%9}, {%0,%1,%2,%3};"
                 : "+f"(c[0]), "+f"(c[1]), "+f"(c[2]), "+f"(c[3])
                 : "r"(a[0]), "r"(a[1]), "r"(a[2]), "r"(a[3]), "r"(b0), "r"(b1));
}
__device__ __forceinline__ void split_wr(__half* hi, __half* lo, size_t idx, float v) {
    __half h = __float2half_rn(v);
    hi[idx] = h;
    lo[idx] = __float2half_rn(v - __half2float(h));
}
// fast sigmoid / tanh via __expf (saturate correctly at +-inf)
__device__ __forceinline__ float fsigmoid(float x) { return 1.f / (1.f + __expf(-x)); }
__device__ __forceinline__ float ftanh(float x)    { return 1.f - 2.f / (__expf(2.f * x) + 1.f); }

// MODE 0: C = A@B^T (+A2@B2^T) (+bias) -> C
// MODE 1: LSTM gate epilogue on interleaved gate columns; updates cst, writes h (hi/lo[, hf])
template<int MODE>
__global__ __launch_bounds__(256, 2) void gemm_wm(
    const __half* __restrict__ Ahi,  const __half* __restrict__ Alo,
    const __half* __restrict__ Bhi,  const __half* __restrict__ Blo,  int K,
    const __half* __restrict__ A2hi, const __half* __restrict__ A2lo,
    const __half* __restrict__ B2hi, const __half* __restrict__ B2lo, int K2,
    const float* __restrict__ bias,
    float* __restrict__ C, int ldC,
    float* __restrict__ cst, float* __restrict__ hf,
    __half* __restrict__ hhi, __half* __restrict__ hlo)
{
    extern __shared__ __half sbuf[];
    const uint32_t sb = smem_u32(sbuf);
    const int tid  = threadIdx.x;
    const int wid  = tid >> 5;
    const int lane = tid & 31;
    const int mBase   = blockIdx.y * 128;
    const int colBase = blockIdx.x * 128;
    const int warpM = (wid >> 2) * 64;
    const int warpN = (wid & 3) * 32;

    const int nc1 = K >> 5;
    const int nc2 = A2hi ? (K2 >> 5) : 0;
    const int nc  = nc1 + nc2;

    float acc[4][4][4];
#pragma unroll
    for (int i = 0; i < 4; i++)
#pragma unroll
        for (int j = 0; j < 4; j++)
#pragma unroll
            for (int q = 0; q < 4; q++) acc[i][j][q] = 0.f;

    auto issue = [&](int ci, int bsel) {
        int pair = (ci >= nc1) ? 1 : 0;
        int k0   = ((pair ? (ci - nc1) : ci) << 5);
        int Kp   = pair ? K2 : K;
        const __half* ah = pair ? A2hi : Ahi;
        const __half* al = pair ? A2lo : Alo;
        const __half* bh = pair ? B2hi : Bhi;
        const __half* bl = pair ? B2lo : Blo;
        uint32_t dB = sb + (uint32_t)bsel * BUFB;
#pragma unroll
        for (int j = 0; j < 2; j++) {
            int u = tid * 2 + j, row = u >> 2, seg = u & 3;
            uint32_t so = (uint32_t)((row * LDSROW + seg * 8) * 2);
            size_t aoff = (size_t)(mBase  + row) * Kp + k0 + seg * 8;
            size_t boff = (size_t)(colBase + row) * Kp + k0 + seg * 8;
            cp16(dB + 0 * CH2 + so, ah + aoff);
            cp16(dB + 1 * CH2 + so, al + aoff);
            cp16(dB + 2 * CH2 + so, bh + boff);
            cp16(dB + 3 * CH2 + so, bl + boff);
        }
        asm volatile("cp.async.commit_group;" ::: "memory");
    };

    issue(0, 0);
    for (int ci = 0; ci < nc; ci++) {
        int bsel = ci & 1;
        if (ci + 1 < nc) {
            issue(ci + 1, bsel ^ 1);
            asm volatile("cp.async.wait_group 1;" ::: "memory");
        } else {
            asm volatile("cp.async.wait_group 0;" ::: "memory");
        }
        __syncthreads();

        const uint32_t base = sb + (uint32_t)bsel * BUFB;
        const uint32_t aHiB = base,           aLoB = base + CH2;
        const uint32_t bHiB = base + 2 * CH2, bLoB = base + 3 * CH2;

#pragma unroll
        for (int ks = 0; ks < 2; ks++) {
            uint32_t ahi_f[4][4], alo_f[4][4], bhi_f[2][4], blo_f[2][4];
#pragma unroll
            for (int mi = 0; mi < 4; mi++) {
                uint32_t off = (uint32_t)(((warpM + mi * 16 + (lane & 15)) * LDSROW
                                           + ks * 16 + (lane >> 4) * 8) * 2);
                ldsm_x4(ahi_f[mi], aHiB + off);
                ldsm_x4(alo_f[mi], aLoB + off);
            }
#pragma unroll
            for (int p = 0; p < 2; p++) {
                uint32_t off = (uint32_t)(((warpN + p * 16 + (lane >> 4) * 8 + (lane & 7)) * LDSROW
                                           + ks * 16 + ((lane >> 3) & 1) * 8) * 2);
                ldsm_x4(bhi_f[p], bHiB + off);
                ldsm_x4(blo_f[p], bLoB + off);
            }
#pragma unroll
            for (int mi = 0; mi < 4; mi++)
#pragma unroll
                for (int p = 0; p < 2; p++)
#pragma unroll
                    for (int q = 0; q < 2; q++) {
                        int ni = p * 2 + q;
                        mma16816(acc[mi][ni], ahi_f[mi], bhi_f[p][q * 2], bhi_f[p][q * 2 + 1]);
                        mma16816(acc[mi][ni], ahi_f[mi], blo_f[p][q * 2], blo_f[p][q * 2 + 1]);
                        mma16816(acc[mi][ni], alo_f[mi], bhi_f[p][q * 2], bhi_f[p][q * 2 + 1]);
                    }
        }
        __syncthreads();
    }

    // ---- epilogue ----
    const int g = lane >> 2, t4 = lane & 3;
    if (MODE == 0) {
#pragma unroll
        for (int mi = 0; mi < 4; mi++) {
            int m0 = mBase + warpM + mi * 16 + g;
#pragma unroll
            for (int ni = 0; ni < 4; ni++) {
                int n = colBase + warpN + ni * 8 + t4 * 2;
                float b0 = 0.f, b1 = 0.f;
                if (bias) { b0 = bias[n]; b1 = bias[n + 1]; }
                float2 v0 = make_float2(acc[mi][ni][0] + b0, acc[mi][ni][1] + b1);
                float2 v1 = make_float2(acc[mi][ni][2] + b0, acc[mi][ni][3] + b1);
                *(float2*)(C + (size_t)m0 * ldC + n) = v0;
                *(float2*)(C + (size_t)(m0 + 8) * ldC + n) = v1;
            }
        }
    } else {
        // interleaved gate columns: col n -> dim d = n>>2, gate q = n&3 (i,f,g,o)
#pragma unroll
        for (int mi = 0; mi < 4; mi++) {
            int m0 = mBase + warpM + mi * 16 + g;
#pragma unroll
            for (int ni = 0; ni < 4; ni++) {
                int n = colBase + warpN + ni * 8 + t4 * 2;
                int d = n >> 2;
                float b0 = bias[n], b1 = bias[n + 1];
                float4 mine;
                mine.x = acc[mi][ni][0] + b0;  // row m0,   col n
                mine.y = acc[mi][ni][1] + b1;  // row m0,   col n+1
                mine.z = acc[mi][ni][2] + b0;  // row m0+8, col n
                mine.w = acc[mi][ni][3] + b1;  // row m0+8, col n+1
                float4 oth;
                oth.x = __shfl_xor_sync(0xffffffffu, mine.x, 1);
                oth.y = __shfl_xor_sync(0xffffffffu, mine.y, 1);
                oth.z = __shfl_xor_sync(0xffffffffu, mine.z, 1);
                oth.w = __shfl_xor_sync(0xffffffffu, mine.w, 1);
                bool evenp = (t4 & 1) == 0;
                float gi = evenp ? mine.x : oth.z;
                float gf = evenp ? mine.y : oth.w;
                float gg = evenp ? oth.x  : mine.z;
                float go = evenp ? oth.y  : mine.w;
                int row = evenp ? m0 : m0 + 8;
                size_t idx = (size_t)row * Hh + d;
                float cn = fsigmoid(gf) * cst[idx] + fsigmoid(gi) * ftanh(gg);
                cst[idx] = cn;
                float hv = fsigmoid(go) * ftanh(cn);
                if (hf) hf[idx] = hv;
                split_wr(hhi, hlo, idx, hv);
            }
        }
    }
}

// ---------------- small prep kernels ----------------
__global__ void transpose_x(const float* __restrict__ x) {
    int idx = blockIdx.x * blockDim.x + threadIdx.x;
    if (idx >= MTOT * Ff) return;
    int f  = idx & 63;
    int r  = idx >> 6;
    int n  = r & (Nn - 1);
    int bt = r >> 11;
    int b  = bt & 3;
    int t  = bt >> 2;
    float v = x[(((size_t)(b * Tt + t) * Nn + n) << 6) + f];
    split_wr(g_xhi, g_xlo, idx, v);
}

__global__ void wt_kernel(const float* __restrict__ W) {
    int i = blockIdx.x * blockDim.x + threadIdx.x;
    if (i >= Hh * Ff) return;
    int n = i >> 6, k = i & 63;
    split_wr(g_wthi, g_wtlo, i, W[k * Hh + n]);
}

// split + interleave LSTM weight rows: new row 4d+q = original row q*128+d
__global__ void split_w(const float* __restrict__ w0, const float* __restrict__ u0,
                        const float* __restrict__ w1, const float* __restrict__ u1) {
    int i = blockIdx.x * blockDim.x + threadIdx.x;
    if (i >= 4 * G4H * Hh) return;
    int which = i >> 16;
    int j = i & 65535;
    int orow = j >> 7, col = j & 127;
    int q = orow >> 7, d = orow & 127;
    int nj = ((d << 2) | q) * 128 + col;
    if      (which == 0) split_wr(g_w0hi, g_w0lo, nj, w0[j]);
    else if (which == 1) split_wr(g_u0hi, g_u0lo, nj, u0[j]);
    else if (which == 2) split_wr(g_w1hi, g_w1lo, nj, w1[j]);
    else                 split_wr(g_u1hi, g_u1lo, nj, u1[j]);
}

__global__ void init_kernel(const float* __restrict__ b_ih0, const float* __restrict__ b_hh0,
                            const float* __restrict__ b_ih1, const float* __restrict__ b_hh1) {
    int i = blockIdx.x * blockDim.x + threadIdx.x;
    if (i < NTOT) g_count[i] = 1;
    if (i < G4H) {
        int q = i >> 7, d = i & 127;
        int ni = (d << 2) | q;
        g_bsum0[ni] = b_ih0[i] + b_hh0[i];
        g_bsum1[ni] = b_ih1[i] + b_hh1[i];
    }
}

__global__ void zero_state() {
    int i = blockIdx.x * blockDim.x + threadIdx.x;
    if (i >= NTOT * Hh) return;
    g_c0[i] = 0.f; g_c1[i] = 0.f;
    __half z = __float2half(0.f);
    g_h0hi[i] = z; g_h0lo[i] = z; g_h1hi[i] = z; g_h1lo[i] = z;  // slot 0
}

__global__ void count_kernel(const int* __restrict__ ei) {
    int e = blockIdx.x * blockDim.x + threadIdx.x;
    if (e < Ee) atomicAdd(&g_count[ei[Ee + e]], 1);
}

__global__ void scan_kernel() {
    __shared__ int part[256];
    int tid  = threadIdx.x;
    int base = tid * 32;
    int local[32];
    int s = 0;
#pragma unroll
    for (int i = 0; i < 32; i++) { local[i] = g_count[base + i]; s += local[i]; }
    part[tid] = s;
    __syncthreads();
    for (int off = 1; off < 256; off <<= 1) {
        int v = (tid >= off) ? part[tid - off] : 0;
        __syncthreads();
        part[tid] += v;
        __syncthreads();
    }
    int run = part[tid] - s;
#pragma unroll
    for (int i = 0; i < 32; i++) {
        g_off[base + i] = run;
        g_cur[base + i] = run;
        run += local[i];
    }
    if (tid == 255) g_off[NTOT] = run;
}

__global__ void fill_kernel(const int* __restrict__ ei) {
    int e = blockIdx.x * blockDim.x + threadIdx.x;
    if (e < Ee) {
        int d = ei[Ee + e];
        int p = atomicAdd(&g_cur[d], 1);
        g_csr[p] = ei[e];
    } else if (e < EFULL) {
        int v = e - Ee;
        int p = atomicAdd(&g_cur[v], 1);
        g_csr[p] = v;
    }
}

// ---------------- per-head attention logits ----------------
__global__ void att_kernel(const float* __restrict__ att_src, const float* __restrict__ att_dst) {
    int gw   = (blockIdx.x * blockDim.x + threadIdx.x) >> 5;
    int lane = threadIdx.x & 31;
    if (gw >= MTOT) return;
    const float* hr = g_h + (size_t)gw * 128;
    float ps[4], pd[4];
#pragma unroll
    for (int j = 0; j < 4; j++) {
        float hv = hr[j * 32 + lane];
        ps[j] = hv * att_src[j * 32 + lane];
        pd[j] = hv * att_dst[j * 32 + lane];
    }
#pragma unroll
    for (int off = 16; off; off >>= 1)
#pragma unroll
        for (int j = 0; j < 4; j++) {
            ps[j] += __shfl_xor_sync(0xffffffffu, ps[j], off);
            pd[j] += __shfl_xor_sync(0xffffffffu, pd[j], off);
        }
    if (lane == 0)
#pragma unroll
        for (int j = 0; j < 4; j++) {
            g_asrc[gw * 4 + j] = ps[j];
            g_adst[gw * 4 + j] = pd[j];
        }
}

// ---------------- GAT edge softmax + aggregation (warp per (node,t)) ----------------
__global__ void gat_kernel(const float* __restrict__ gat_bias) {
    int warp = threadIdx.x >> 5;
    int lane = threadIdx.x & 31;
    int node = blockIdx.x * 8 + warp;
    int t    = blockIdx.y;
    int beg  = g_off[node], end = g_off[node + 1];

    float ad[4];
#pragma unroll
    for (int j = 0; j < 4; j++) ad[j] = g_adst[(t * NTOT + node) * 4 + j];

    float mx[4] = {-1e30f, -1e30f, -1e30f, -1e30f};
    for (int e = beg + lane; e < end; e += 32) {
        int s = g_csr[e];
        const float* as = g_asrc + (t * NTOT + s) * 4;
#pragma unroll
        for (int j = 0; j < 4; j++) {
            float v = as[j] + ad[j];
            v = v > 0.f ? v : 0.2f * v;
            mx[j] = fmaxf(mx[j], v);
        }
    }
#pragma unroll
    for (int off = 16; off; off >>= 1)
#pragma unroll
        for (int j = 0; j < 4; j++) mx[j] = fmaxf(mx[j], __shfl_xor_sync(0xffffffffu, mx[j], off));

    float den[4] = {0.f, 0.f, 0.f, 0.f};
    for (int e = beg + lane; e < end; e += 32) {
        int s = g_csr[e];
        const float* as = g_asrc + (t * NTOT + s) * 4;
#pragma unroll
        for (int j = 0; j < 4; j++) {
            float v = as[j] + ad[j];
            v = v > 0.f ? v : 0.2f * v;
            den[j] += __expf(v - mx[j]);
        }
    }
#pragma unroll
    for (int off = 16; off; off >>= 1)
#pragma unroll
        for (int j = 0; j < 4; j++) den[j] += __shfl_xor_sync(0xffffffffu, den[j], off);

    float rden[4];
#pragma unroll
    for (int j = 0; j < 4; j++) rden[j] = 1.f / den[j];

    float acc[4] = {0.f, 0.f, 0.f, 0.f};
    for (int e = beg; e < end; e++) {
        int s = g_csr[e];
        const float* as = g_asrc + (t * NTOT + s) * 4;
        const float* hs = g_h + (size_t)(t * NTOT + s) * 128;
#pragma unroll
        for (int j = 0; j < 4; j++) {
            float v = as[j] + ad[j];
            v = v > 0.f ? v : 0.2f * v;
            float w = __expf(v - mx[j]) * rden[j];
            acc[j] += w * hs[j * 32 + lane];
        }
    }
#pragma unroll
    for (int j = 0; j < 4; j++) {
        int d = j * 32 + lane;
        float r = fmaxf(acc[j] + gat_bias[d], 0.f);
        split_wr(g_sphi, g_splo, (size_t)(t * NTOT + node) * 128 + d, r);
    }
}

// ---------------- LayerNorm ----------------
__global__ void ln_kernel(const float* __restrict__ gamma, const float* __restrict__ beta,
                          float* __restrict__ out) {
    int gw   = (blockIdx.x * blockDim.x + threadIdx.x) >> 5;
    int lane = threadIdx.x & 31;
    if (gw >= NTOT) return;
    const float* hr = g_h1f + (size_t)gw * 128;
    float v[4];
    float s = 0.f, ss = 0.f;
#pragma unroll
    for (int j = 0; j < 4; j++) {
        v[j] = hr[j * 32 + lane];
        s += v[j];
        ss += v[j] * v[j];
    }
#pragma unroll
    for (int off = 16; off; off >>= 1) {
        s  += __shfl_xor_sync(0xffffffffu, s, off);
        ss += __shfl_xor_sync(0xffffffffu, ss, off);
    }
    float mu   = s * (1.f / 128.f);
    float var  = ss * (1.f / 128.f) - mu * mu;
    float rstd = rsqrtf(var + 1e-5f);
#pragma unroll
    for (int j = 0; j < 4; j++) {
        int d = j * 32 + lane;
        out[(size_t)gw * 128 + d] = (v[j] - mu) * rstd * gamma[d] + beta[d];
    }
}

// ---------------- launch ----------------
template <typename T>
static T* sym(const void* s) { void* p = nullptr; cudaGetSymbolAddress(&p, s); return (T*)p; }

extern "C" void kernel_launch(void* const* d_in, const int* in_sizes, int n_in,
                              void* d_out, int out_size) {
    const float* x        = (const float*)d_in[0];
    const float* W        = (const float*)d_in[1];
    const float* att_src  = (const float*)d_in[2];
    const float* att_dst  = (const float*)d_in[3];
    const float* gat_bias = (const float*)d_in[4];
    const float* W_ih0    = (const float*)d_in[5];
    const float* W_hh0    = (const float*)d_in[6];
    const float* b_ih0    = (const float*)d_in[7];
    const float* b_hh0    = (const float*)d_in[8];
    const float* W_ih1    = (const float*)d_in[9];
    const float* W_hh1    = (const float*)d_in[10];
    const float* b_ih1    = (const float*)d_in[11];
    const float* b_hh1    = (const float*)d_in[12];
    const float* ln_gamma = (const float*)d_in[13];
    const float* ln_beta  = (const float*)d_in[14];
    const int*   edge_index = (const int*)d_in[15];
    float* out = (float*)d_out;

    __half* p_xhi  = sym<__half>(g_xhi);  __half* p_xlo  = sym<__half>(g_xlo);
    __half* p_wthi = sym<__half>(g_wthi); __half* p_wtlo = sym<__half>(g_wtlo);
    __half* p_sphi = sym<__half>(g_sphi); __half* p_splo = sym<__half>(g_splo);
    __half* p_w0hi = sym<__half>(g_w0hi); __half* p_w0lo = sym<__half>(g_w0lo);
    __half* p_u0hi = sym<__half>(g_u0hi); __half* p_u0lo = sym<__half>(g_u0lo);
    __half* p_w1hi = sym<__half>(g_w1hi); __half* p_w1lo = sym<__half>(g_w1lo);
    __half* p_u1hi = sym<__half>(g_u1hi); __half* p_u1lo = sym<__half>(g_u1lo);
    __half* p_h0hi = sym<__half>(g_h0hi); __half* p_h0lo = sym<__half>(g_h0lo);
    __half* p_h1hi = sym<__half>(g_h1hi); __half* p_h1lo = sym<__half>(g_h1lo);
    float* p_h     = sym<float>(g_h);
    float* p_c0    = sym<float>(g_c0);
    float* p_c1    = sym<float>(g_c1);
    float* p_h1f   = sym<float>(g_h1f);
    float* p_bsum0 = sym<float>(g_bsum0);
    float* p_bsum1 = sym<float>(g_bsum1);

    const int smemB = 2 * BUFB;   // 81920
    cudaFuncSetAttribute(gemm_wm<0>, cudaFuncAttributeMaxDynamicSharedMemorySize, smemB);
    cudaFuncSetAttribute(gemm_wm<1>, cudaFuncAttributeMaxDynamicSharedMemorySize, smemB);

    const size_t SLOT = (size_t)NTOT * Hh;

    // launches 1-5 (ncu -s 5 -c 1 captures launch #6 = projection GEMM)
    transpose_x<<<(MTOT * Ff + 255) / 256, 256>>>(x);
    wt_kernel<<<(Hh * Ff + 255) / 256, 256>>>(W);
    split_w<<<(4 * G4H * Hh + 255) / 256, 256>>>(W_ih0, W_hh0, W_ih1, W_hh1);
    init_kernel<<<(NTOT + 255) / 256, 256>>>(b_ih0, b_hh0, b_ih1, b_hh1);
    zero_state<<<(NTOT * Hh + 255) / 256, 256>>>();

    // launch 6: h = x_flat @ Wt^T  (M=81920, N=128, K=64)
    gemm_wm<0><<<dim3(1, MTOT / 128), 256, smemB>>>(
        p_xhi, p_xlo, p_wthi, p_wtlo, Ff,
        nullptr, nullptr, nullptr, nullptr, 0,
        nullptr, p_h, Hh, nullptr, nullptr, nullptr, nullptr);

    count_kernel<<<(Ee + 255) / 256, 256>>>(edge_index);
    scan_kernel<<<1, 256>>>();
    fill_kernel<<<(EFULL + 255) / 256, 256>>>(edge_index);
    att_kernel<<<(MTOT * 32 + 255) / 256, 256>>>(att_src, att_dst);
    gat_kernel<<<dim3(NTOT / 8, Tt), 256>>>(gat_bias);

    for (int t = 0; t < Tt; t++) {
        // layer 0: gates = spatial[t]@W0^T + h0[t]@U0^T + bsum0 -> fused -> h0[t+1], c0
        gemm_wm<1><<<dim3(4, NTOT / 128), 256, smemB>>>(
            p_sphi + (size_t)t * SLOT, p_splo + (size_t)t * SLOT, p_w0hi, p_w0lo, Hh,
            p_h0hi + (size_t)t * SLOT, p_h0lo + (size_t)t * SLOT, p_u0hi, p_u0lo, Hh,
            p_bsum0, nullptr, G4H,
            p_c0, nullptr, p_h0hi + (size_t)(t + 1) * SLOT, p_h0lo + (size_t)(t + 1) * SLOT);
        // layer 1: gates = h0[t+1]@W1^T + h1[t]@U1^T + bsum1 -> fused -> h1[t+1], c1, h1f
        gemm_wm<1><<<dim3(4, NTOT / 128), 256, smemB>>>(
            p_h0hi + (size_t)(t + 1) * SLOT, p_h0lo + (size_t)(t + 1) * SLOT, p_w1hi, p_w1lo, Hh,
            p_h1hi + (size_t)t * SLOT, p_h1lo + (size_t)t * SLOT, p_u1hi, p_u1lo, Hh,
            p_bsum1, nullptr, G4H,
            p_c1, p_h1f, p_h1hi + (size_t)(t + 1) * SLOT, p_h1lo + (size_t)(t + 1) * SLOT);
    }

    ln_kernel<<<(NTOT * 32 + 255) / 256, 256>>>(ln_gamma, ln_beta, out);
}

// round 15
// speedup vs baseline: 1.2713x; 1.2176x over previous
#include <cuda_runtime.h>
#include <cuda_fp16.h>
#include <math.h>
#include <stdint.h>

#define Bb    4
#define Tt    10
#define Nn    2048
#define Ff    64
#define Hh    128
#define NHEAD 4
#define Dd    32
#define Ee    65536
#define NTOT  8192            // B*N
#define MTOT  81920           // T*NTOT
#define G4H   512             // 4*H
#define EFULL (Ee + NTOT)     // edges + self loops

// ---------------- device scratch (no allocations allowed) ----------------
__device__ __align__(16) __half g_xhi[MTOT * Ff],  g_xlo[MTOT * Ff];
__device__ __align__(16) __half g_wthi[Hh * Ff],   g_wtlo[Hh * Ff];
__device__ __align__(16) __half g_sphi[MTOT * Hh], g_splo[MTOT * Hh];
// LSTM weights, rows interleaved: new row 4d+q = original row q*128+d
__device__ __align__(16) __half g_w0hi[G4H * Hh],  g_w0lo[G4H * Hh];   // W_ih0
__device__ __align__(16) __half g_u0hi[G4H * Hh],  g_u0lo[G4H * Hh];   // W_hh0
__device__ __align__(16) __half g_w1hi[G4H * Hh],  g_w1lo[G4H * Hh];   // W_ih1
__device__ __align__(16) __half g_u1hi[G4H * Hh],  g_u1lo[G4H * Hh];   // W_hh1
// time-ringed recurrent state (slot t read, slot t+1 written)
__device__ __align__(16) __half g_h0hi[(Tt + 1) * NTOT * Hh], g_h0lo[(Tt + 1) * NTOT * Hh];
__device__ __align__(16) __half g_h1hi[(Tt + 1) * NTOT * Hh], g_h1lo[(Tt + 1) * NTOT * Hh];

__device__ float g_h[MTOT * Hh];        // GAT projections (fp32)
__device__ float g_c0[NTOT * Hh];
__device__ float g_c1[NTOT * Hh];
__device__ float g_h1f[NTOT * Hh];      // fp32 h1 for LayerNorm
__device__ float g_bsum0[G4H];          // interleaved
__device__ float g_bsum1[G4H];          // interleaved
__device__ float g_asrc[MTOT * NHEAD];
__device__ float g_adst[MTOT * NHEAD];
__device__ int   g_count[NTOT];
__device__ int   g_off[NTOT + 1];
__device__ int   g_cur[NTOT];
__device__ int   g_csr[EFULL];

// ============================ warp-MMA fp16x3 GEMM ============================
#define LDSROW   40
#define CHUNK_H  (128 * LDSROW)
#define CH2      (CHUNK_H * 2)
#define BUFB     (4 * CH2)

__device__ __forceinline__ uint32_t smem_u32(const void* p) {
    return (uint32_t)__cvta_generic_to_shared(p);
}
__device__ __forceinline__ void cp16(uint32_t dst, const void* src) {
    asm volatile("cp.async.ca.shared.global [%0], [%1], 16;" :: "r"(dst), "l"(src));
}
__device__ __forceinline__ void ldsm_x4(uint32_t (&r)[4], uint32_t addr) {
    asm volatile("ldmatrix.sync.aligned.m8n8.x4.shared.b16 {%0,%1,%2,%3}, [%4];"
                 : "=r"(r[0]), "=r"(r[1]), "=r"(r[2]), "=r"(r[3]) : "r"(addr));
}
__device__ __forceinline__ void mma16816(float (&c)[4], const uint32_t (&a)[4],
                                         uint32_t b0, uint32_t b1) {
    asm volatile("mma.sync.aligned.m16n8k16.row.col.f32.f16.f16.f32 "
                 "{%0,%1,%2,%3}, {%4,%5,%6,%7}, {%8,%9}, {%0,%1,%2,%3};"
                 : "+f"(c[0]), "+f"(c[1]), "+f"(c[2]), "+f"(c[3])
                 : "r"(a[0]), "r"(a[1]), "r"(a[2]), "r"(a[3]), "r"(b0), "r"(b1));
}
__device__ __forceinline__ void split_wr(__half* hi, __half* lo, size_t idx, float v) {
    __half h = __float2half_rn(v);
    hi[idx] = h;
    lo[idx] = __float2half_rn(v - __half2float(h));
}
// fast sigmoid / tanh via __expf (saturate correctly at +-inf)
__device__ __forceinline__ float fsigmoid(float x) { return 1.f / (1.f + __expf(-x)); }
__device__ __forceinline__ float ftanh(float x)    { return 1.f - 2.f / (__expf(2.f * x) + 1.f); }

// MODE 0: C = A@B^T (+A2@B2^T) (+bias) -> C
// MODE 1: LSTM gate epilogue (interleaved gate cols), SMEM-staged coalesced I/O
template<int MODE>
__global__ __launch_bounds__(256, 2) void gemm_wm(
    const __half* __restrict__ Ahi,  const __half* __restrict__ Alo,
    const __half* __restrict__ Bhi,  const __half* __restrict__ Blo,  int K,
    const __half* __restrict__ A2hi, const __half* __restrict__ A2lo,
    const __half* __restrict__ B2hi, const __half* __restrict__ B2lo, int K2,
    const float* __restrict__ bias,
    float* __restrict__ C, int ldC,
    float* __restrict__ cst, float* __restrict__ hf,
    __half* __restrict__ hhi, __half* __restrict__ hlo)
{
    extern __shared__ __half sbuf[];
    const uint32_t sb = smem_u32(sbuf);
    const int tid  = threadIdx.x;
    const int wid  = tid >> 5;
    const int lane = tid & 31;
    const int mBase   = blockIdx.y * 128;
    const int colBase = blockIdx.x * 128;
    const int warpM = (wid >> 2) * 64;
    const int warpN = (wid & 3) * 32;

    const int nc1 = K >> 5;
    const int nc2 = A2hi ? (K2 >> 5) : 0;
    const int nc  = nc1 + nc2;

    float acc[4][4][4];
#pragma unroll
    for (int i = 0; i < 4; i++)
#pragma unroll
        for (int j = 0; j < 4; j++)
#pragma unroll
            for (int q = 0; q < 4; q++) acc[i][j][q] = 0.f;

    auto issue = [&](int ci, int bsel) {
        int pair = (ci >= nc1) ? 1 : 0;
        int k0   = ((pair ? (ci - nc1) : ci) << 5);
        int Kp   = pair ? K2 : K;
        const __half* ah = pair ? A2hi : Ahi;
        const __half* al = pair ? A2lo : Alo;
        const __half* bh = pair ? B2hi : Bhi;
        const __half* bl = pair ? B2lo : Blo;
        uint32_t dB = sb + (uint32_t)bsel * BUFB;
#pragma unroll
        for (int j = 0; j < 2; j++) {
            int u = tid * 2 + j, row = u >> 2, seg = u & 3;
            uint32_t so = (uint32_t)((row * LDSROW + seg * 8) * 2);
            size_t aoff = (size_t)(mBase  + row) * Kp + k0 + seg * 8;
            size_t boff = (size_t)(colBase + row) * Kp + k0 + seg * 8;
            cp16(dB + 0 * CH2 + so, ah + aoff);
            cp16(dB + 1 * CH2 + so, al + aoff);
            cp16(dB + 2 * CH2 + so, bh + boff);
            cp16(dB + 3 * CH2 + so, bl + boff);
        }
        asm volatile("cp.async.commit_group;" ::: "memory");
    };

    issue(0, 0);
    for (int ci = 0; ci < nc; ci++) {
        int bsel = ci & 1;
        if (ci + 1 < nc) {
            issue(ci + 1, bsel ^ 1);
            asm volatile("cp.async.wait_group 1;" ::: "memory");
        } else {
            asm volatile("cp.async.wait_group 0;" ::: "memory");
        }
        __syncthreads();

        const uint32_t base = sb + (uint32_t)bsel * BUFB;
        const uint32_t aHiB = base,           aLoB = base + CH2;
        const uint32_t bHiB = base + 2 * CH2, bLoB = base + 3 * CH2;

#pragma unroll
        for (int ks = 0; ks < 2; ks++) {
            uint32_t ahi_f[4][4], alo_f[4][4], bhi_f[2][4], blo_f[2][4];
#pragma unroll
            for (int mi = 0; mi < 4; mi++) {
                uint32_t off = (uint32_t)(((warpM + mi * 16 + (lane & 15)) * LDSROW
                                           + ks * 16 + (lane >> 4) * 8) * 2);
                ldsm_x4(ahi_f[mi], aHiB + off);
                ldsm_x4(alo_f[mi], aLoB + off);
            }
#pragma unroll
            for (int p = 0; p < 2; p++) {
                uint32_t off = (uint32_t)(((warpN + p * 16 + (lane >> 4) * 8 + (lane & 7)) * LDSROW
                                           + ks * 16 + ((lane >> 3) & 1) * 8) * 2);
                ldsm_x4(bhi_f[p], bHiB + off);
                ldsm_x4(blo_f[p], bLoB + off);
            }
#pragma unroll
            for (int mi = 0; mi < 4; mi++)
#pragma unroll
                for (int p = 0; p < 2; p++)
#pragma unroll
                    for (int q = 0; q < 2; q++) {
                        int ni = p * 2 + q;
                        mma16816(acc[mi][ni], ahi_f[mi], bhi_f[p][q * 2], bhi_f[p][q * 2 + 1]);
                        mma16816(acc[mi][ni], ahi_f[mi], blo_f[p][q * 2], blo_f[p][q * 2 + 1]);
                        mma16816(acc[mi][ni], alo_f[mi], bhi_f[p][q * 2], bhi_f[p][q * 2 + 1]);
                    }
        }
        __syncthreads();
    }

    // ---- epilogue ----
    const int g = lane >> 2, t4 = lane & 3;
    if (MODE == 0) {
#pragma unroll
        for (int mi = 0; mi < 4; mi++) {
            int m0 = mBase + warpM + mi * 16 + g;
#pragma unroll
            for (int ni = 0; ni < 4; ni++) {
                int n = colBase + warpN + ni * 8 + t4 * 2;
                float b0 = 0.f, b1 = 0.f;
                if (bias) { b0 = bias[n]; b1 = bias[n + 1]; }
                float2 v0 = make_float2(acc[mi][ni][0] + b0, acc[mi][ni][1] + b1);
                float2 v1 = make_float2(acc[mi][ni][2] + b0, acc[mi][ni][3] + b1);
                *(float2*)(C + (size_t)m0 * ldC + n) = v0;
                *(float2*)(C + (size_t)(m0 + 8) * ldC + n) = v1;
            }
        }
    } else {
        // SMEM-staged LSTM epilogue.
        // Tile: rows mBase..mBase+127, dims cBase..cBase+31 (cBase = colBase/4).
        float* scold = (float*)sbuf;              // [128][33]  c_old -> c_new
        float* shv   = (float*)sbuf + 128 * 33;   // [128][33]  h value
        const int cBase = colBase >> 2;

        // 1) coalesced load of c tile
#pragma unroll
        for (int i = 0; i < 16; i++) {
            int e = tid + i * 256;
            int r = e >> 5, cix = e & 31;
            scold[r * 33 + cix] = cst[(size_t)(mBase + r) * Hh + cBase + cix];
        }
        __syncthreads();

        // 2) gate math; scatter within SMEM only
#pragma unroll
        for (int mi = 0; mi < 4; mi++) {
            int m0 = mBase + warpM + mi * 16 + g;
#pragma unroll
            for (int ni = 0; ni < 4; ni++) {
                int n = colBase + warpN + ni * 8 + t4 * 2;
                int d = n >> 2;
                float b0 = bias[n], b1 = bias[n + 1];
                float4 mine;
                mine.x = acc[mi][ni][0] + b0;  // row m0,   col n
                mine.y = acc[mi][ni][1] + b1;  // row m0,   col n+1
                mine.z = acc[mi][ni][2] + b0;  // row m0+8, col n
                mine.w = acc[mi][ni][3] + b1;  // row m0+8, col n+1
                float4 oth;
                oth.x = __shfl_xor_sync(0xffffffffu, mine.x, 1);
                oth.y = __shfl_xor_sync(0xffffffffu, mine.y, 1);
                oth.z = __shfl_xor_sync(0xffffffffu, mine.z, 1);
                oth.w = __shfl_xor_sync(0xffffffffu, mine.w, 1);
                bool evenp = (t4 & 1) == 0;
                float gi = evenp ? mine.x : oth.z;
                float gf = evenp ? mine.y : oth.w;
                float gg = evenp ? oth.x  : mine.z;
                float go = evenp ? oth.y  : mine.w;
                int row = evenp ? m0 : m0 + 8;
                int sidx = (row - mBase) * 33 + (d - cBase);
                float cn = fsigmoid(gf) * scold[sidx] + fsigmoid(gi) * ftanh(gg);
                scold[sidx] = cn;
                shv[sidx]   = fsigmoid(go) * ftanh(cn);
            }
        }
        __syncthreads();

        // 3) coalesced writeout
#pragma unroll
        for (int i = 0; i < 16; i++) {
            int e = tid + i * 256;
            int r = e >> 5, cix = e & 31;
            size_t gidx = (size_t)(mBase + r) * Hh + cBase + cix;
            float cn = scold[r * 33 + cix];
            float hv = shv[r * 33 + cix];
            cst[gidx] = cn;
            if (hf) hf[gidx] = hv;
            __half hh = __float2half_rn(hv);
            hhi[gidx] = hh;
            hlo[gidx] = __float2half_rn(hv - __half2float(hh));
        }
    }
}

// ---------------- small prep kernels ----------------
__global__ void transpose_x(const float* __restrict__ x) {
    int idx = blockIdx.x * blockDim.x + threadIdx.x;
    if (idx >= MTOT * Ff) return;
    int f  = idx & 63;
    int r  = idx >> 6;
    int n  = r & (Nn - 1);
    int bt = r >> 11;
    int b  = bt & 3;
    int t  = bt >> 2;
    float v = x[(((size_t)(b * Tt + t) * Nn + n) << 6) + f];
    split_wr(g_xhi, g_xlo, idx, v);
}

__global__ void wt_kernel(const float* __restrict__ W) {
    int i = blockIdx.x * blockDim.x + threadIdx.x;
    if (i >= Hh * Ff) return;
    int n = i >> 6, k = i & 63;
    split_wr(g_wthi, g_wtlo, i, W[k * Hh + n]);
}

// split + interleave LSTM weight rows: new row 4d+q = original row q*128+d
__global__ void split_w(const float* __restrict__ w0, const float* __restrict__ u0,
                        const float* __restrict__ w1, const float* __restrict__ u1) {
    int i = blockIdx.x * blockDim.x + threadIdx.x;
    if (i >= 4 * G4H * Hh) return;
    int which = i >> 16;
    int j = i & 65535;
    int orow = j >> 7, col = j & 127;
    int q = orow >> 7, d = orow & 127;
    int nj = ((d << 2) | q) * 128 + col;
    if      (which == 0) split_wr(g_w0hi, g_w0lo, nj, w0[j]);
    else if (which == 1) split_wr(g_u0hi, g_u0lo, nj, u0[j]);
    else if (which == 2) split_wr(g_w1hi, g_w1lo, nj, w1[j]);
    else                 split_wr(g_u1hi, g_u1lo, nj, u1[j]);
}

__global__ void init_kernel(const float* __restrict__ b_ih0, const float* __restrict__ b_hh0,
                            const float* __restrict__ b_ih1, const float* __restrict__ b_hh1) {
    int i = blockIdx.x * blockDim.x + threadIdx.x;
    if (i < NTOT) g_count[i] = 1;
    if (i < G4H) {
        int q = i >> 7, d = i & 127;
        int ni = (d << 2) | q;
        g_bsum0[ni] = b_ih0[i] + b_hh0[i];
        g_bsum1[ni] = b_ih1[i] + b_hh1[i];
    }
}

__global__ void zero_state() {
    int i = blockIdx.x * blockDim.x + threadIdx.x;
    if (i >= NTOT * Hh) return;
    g_c0[i] = 0.f; g_c1[i] = 0.f;
    __half z = __float2half(0.f);
    g_h0hi[i] = z; g_h0lo[i] = z; g_h1hi[i] = z; g_h1lo[i] = z;  // slot 0
}

__global__ void count_kernel(const int* __restrict__ ei) {
    int e = blockIdx.x * blockDim.x + threadIdx.x;
    if (e < Ee) atomicAdd(&g_count[ei[Ee + e]], 1);
}

__global__ void scan_kernel() {
    __shared__ int part[256];
    int tid  = threadIdx.x;
    int base = tid * 32;
    int local[32];
    int s = 0;
#pragma unroll
    for (int i = 0; i < 32; i++) { local[i] = g_count[base + i]; s += local[i]; }
    part[tid] = s;
    __syncthreads();
    for (int off = 1; off < 256; off <<= 1) {
        int v = (tid >= off) ? part[tid - off] : 0;
        __syncthreads();
        part[tid] += v;
        __syncthreads();
    }
    int run = part[tid] - s;
#pragma unroll
    for (int i = 0; i < 32; i++) {
        g_off[base + i] = run;
        g_cur[base + i] = run;
        run += local[i];
    }
    if (tid == 255) g_off[NTOT] = run;
}

__global__ void fill_kernel(const int* __restrict__ ei) {
    int e = blockIdx.x * blockDim.x + threadIdx.x;
    if (e < Ee) {
        int d = ei[Ee + e];
        int p = atomicAdd(&g_cur[d], 1);
        g_csr[p] = ei[e];
    } else if (e < EFULL) {
        int v = e - Ee;
        int p = atomicAdd(&g_cur[v], 1);
        g_csr[p] = v;
    }
}

// ---------------- per-head attention logits ----------------
__global__ void att_kernel(const float* __restrict__ att_src, const float* __restrict__ att_dst) {
    int gw   = (blockIdx.x * blockDim.x + threadIdx.x) >> 5;
    int lane = threadIdx.x & 31;
    if (gw >= MTOT) return;
    const float* hr = g_h + (size_t)gw * 128;
    float ps[4], pd[4];
#pragma unroll
    for (int j = 0; j < 4; j++) {
        float hv = hr[j * 32 + lane];
        ps[j] = hv * att_src[j * 32 + lane];
        pd[j] = hv * att_dst[j * 32 + lane];
    }
#pragma unroll
    for (int off = 16; off; off >>= 1)
#pragma unroll
        for (int j = 0; j < 4; j++) {
            ps[j] += __shfl_xor_sync(0xffffffffu, ps[j], off);
            pd[j] += __shfl_xor_sync(0xffffffffu, pd[j], off);
        }
    if (lane == 0)
#pragma unroll
        for (int j = 0; j < 4; j++) {
            g_asrc[gw * 4 + j] = ps[j];
            g_adst[gw * 4 + j] = pd[j];
        }
}

// ---------------- GAT edge softmax + aggregation (warp per (node,t)) ----------------
__global__ void gat_kernel(const float* __restrict__ gat_bias) {
    int warp = threadIdx.x >> 5;
    int lane = threadIdx.x & 31;
    int node = blockIdx.x * 8 + warp;
    int t    = blockIdx.y;
    int beg  = g_off[node], end = g_off[node + 1];

    float ad[4];
#pragma unroll
    for (int j = 0; j < 4; j++) ad[j] = g_adst[(t * NTOT + node) * 4 + j];

    float mx[4] = {-1e30f, -1e30f, -1e30f, -1e30f};
    for (int e = beg + lane; e < end; e += 32) {
        int s = g_csr[e];
        const float* as = g_asrc + (t * NTOT + s) * 4;
#pragma unroll
        for (int j = 0; j < 4; j++) {
            float v = as[j] + ad[j];
            v = v > 0.f ? v : 0.2f * v;
            mx[j] = fmaxf(mx[j], v);
        }
    }
#pragma unroll
    for (int off = 16; off; off >>= 1)
#pragma unroll
        for (int j = 0; j < 4; j++) mx[j] = fmaxf(mx[j], __shfl_xor_sync(0xffffffffu, mx[j], off));

    float den[4] = {0.f, 0.f, 0.f, 0.f};
    for (int e = beg + lane; e < end; e += 32) {
        int s = g_csr[e];
        const float* as = g_asrc + (t * NTOT + s) * 4;
#pragma unroll
        for (int j = 0; j < 4; j++) {
            float v = as[j] + ad[j];
            v = v > 0.f ? v : 0.2f * v;
            den[j] += __expf(v - mx[j]);
        }
    }
#pragma unroll
    for (int off = 16; off; off >>= 1)
#pragma unroll
        for (int j = 0; j < 4; j++) den[j] += __shfl_xor_sync(0xffffffffu, den[j], off);

    float rden[4];
#pragma unroll
    for (int j = 0; j < 4; j++) rden[j] = 1.f / den[j];

    float acc[4] = {0.f, 0.f, 0.f, 0.f};
    for (int e = beg; e < end; e++) {
        int s = g_csr[e];
        const float* as = g_asrc + (t * NTOT + s) * 4;
        const float* hs = g_h + (size_t)(t * NTOT + s) * 128;
#pragma unroll
        for (int j = 0; j < 4; j++) {
            float v = as[j] + ad[j];
            v = v > 0.f ? v : 0.2f * v;
            float w = __expf(v - mx[j]) * rden[j];
            acc[j] += w * hs[j * 32 + lane];
        }
    }
#pragma unroll
    for (int j = 0; j < 4; j++) {
        int d = j * 32 + lane;
        float r = fmaxf(acc[j] + gat_bias[d], 0.f);
        split_wr(g_sphi, g_splo, (size_t)(t * NTOT + node) * 128 + d, r);
    }
}

// ---------------- LayerNorm ----------------
__global__ void ln_kernel(const float* __restrict__ gamma, const float* __restrict__ beta,
                          float* __restrict__ out) {
    int gw   = (blockIdx.x * blockDim.x + threadIdx.x) >> 5;
    int lane = threadIdx.x & 31;
    if (gw >= NTOT) return;
    const float* hr = g_h1f + (size_t)gw * 128;
    float v[4];
    float s = 0.f, ss = 0.f;
#pragma unroll
    for (int j = 0; j < 4; j++) {
        v[j] = hr[j * 32 + lane];
        s += v[j];
        ss += v[j] * v[j];
    }
#pragma unroll
    for (int off = 16; off; off >>= 1) {
        s  += __shfl_xor_sync(0xffffffffu, s, off);
        ss += __shfl_xor_sync(0xffffffffu, ss, off);
    }
    float mu   = s * (1.f / 128.f);
    float var  = ss * (1.f / 128.f) - mu * mu;
    float rstd = rsqrtf(var + 1e-5f);
#pragma unroll
    for (int j = 0; j < 4; j++) {
        int d = j * 32 + lane;
        out[(size_t)gw * 128 + d] = (v[j] - mu) * rstd * gamma[d] + beta[d];
    }
}

// ---------------- launch ----------------
template <typename T>
static T* sym(const void* s) { void* p = nullptr; cudaGetSymbolAddress(&p, s); return (T*)p; }

extern "C" void kernel_launch(void* const* d_in, const int* in_sizes, int n_in,
                              void* d_out, int out_size) {
    const float* x        = (const float*)d_in[0];
    const float* W        = (const float*)d_in[1];
    const float* att_src  = (const float*)d_in[2];
    const float* att_dst  = (const float*)d_in[3];
    const float* gat_bias = (const float*)d_in[4];
    const float* W_ih0    = (const float*)d_in[5];
    const float* W_hh0    = (const float*)d_in[6];
    const float* b_ih0    = (const float*)d_in[7];
    const float* b_hh0    = (const float*)d_in[8];
    const float* W_ih1    = (const float*)d_in[9];
    const float* W_hh1    = (const float*)d_in[10];
    const float* b_ih1    = (const float*)d_in[11];
    const float* b_hh1    = (const float*)d_in[12];
    const float* ln_gamma = (const float*)d_in[13];
    const float* ln_beta  = (const float*)d_in[14];
    const int*   edge_index = (const int*)d_in[15];
    float* out = (float*)d_out;

    __half* p_xhi  = sym<__half>(g_xhi);  __half* p_xlo  = sym<__half>(g_xlo);
    __half* p_wthi = sym<__half>(g_wthi); __half* p_wtlo = sym<__half>(g_wtlo);
    __half* p_sphi = sym<__half>(g_sphi); __half* p_splo = sym<__half>(g_splo);
    __half* p_w0hi = sym<__half>(g_w0hi); __half* p_w0lo = sym<__half>(g_w0lo);
    __half* p_u0hi = sym<__half>(g_u0hi); __half* p_u0lo = sym<__half>(g_u0lo);
    __half* p_w1hi = sym<__half>(g_w1hi); __half* p_w1lo = sym<__half>(g_w1lo);
    __half* p_u1hi = sym<__half>(g_u1hi); __half* p_u1lo = sym<__half>(g_u1lo);
    __half* p_h0hi = sym<__half>(g_h0hi); __half* p_h0lo = sym<__half>(g_h0lo);
    __half* p_h1hi = sym<__half>(g_h1hi); __half* p_h1lo = sym<__half>(g_h1lo);
    float* p_h     = sym<float>(g_h);
    float* p_c0    = sym<float>(g_c0);
    float* p_c1    = sym<float>(g_c1);
    float* p_h1f   = sym<float>(g_h1f);
    float* p_bsum0 = sym<float>(g_bsum0);
    float* p_bsum1 = sym<float>(g_bsum1);

    const int smemB = 2 * BUFB;   // 163840 bytes... no: BUFB=40960, 2*BUFB=81920
    cudaFuncSetAttribute(gemm_wm<0>, cudaFuncAttributeMaxDynamicSharedMemorySize, smemB);
    cudaFuncSetAttribute(gemm_wm<1>, cudaFuncAttributeMaxDynamicSharedMemorySize, smemB);

    const size_t SLOT = (size_t)NTOT * Hh;

    // launches 1-5 (ncu -s 5 -c 1 captures launch #6 = projection GEMM)
    transpose_x<<<(MTOT * Ff + 255) / 256, 256>>>(x);
    wt_kernel<<<(Hh * Ff + 255) / 256, 256>>>(W);
    split_w<<<(4 * G4H * Hh + 255) / 256, 256>>>(W_ih0, W_hh0, W_ih1, W_hh1);
    init_kernel<<<(NTOT + 255) / 256, 256>>>(b_ih0, b_hh0, b_ih1, b_hh1);
    zero_state<<<(NTOT * Hh + 255) / 256, 256>>>();

    // launch 6: h = x_flat @ Wt^T  (M=81920, N=128, K=64)
    gemm_wm<0><<<dim3(1, MTOT / 128), 256, smemB>>>(
        p_xhi, p_xlo, p_wthi, p_wtlo, Ff,
        nullptr, nullptr, nullptr, nullptr, 0,
        nullptr, p_h, Hh, nullptr, nullptr, nullptr, nullptr);

    count_kernel<<<(Ee + 255) / 256, 256>>>(edge_index);
    scan_kernel<<<1, 256>>>();
    fill_kernel<<<(EFULL + 255) / 256, 256>>>(edge_index);
    att_kernel<<<(MTOT * 32 + 255) / 256, 256>>>(att_src, att_dst);
    gat_kernel<<<dim3(NTOT / 8, Tt), 256>>>(gat_bias);

    for (int t = 0; t < Tt; t++) {
        // layer 0: gates = spatial[t]@W0^T + h0[t]@U0^T + bsum0 -> fused -> h0[t+1], c0
        gemm_wm<1><<<dim3(4, NTOT / 128), 256, smemB>>>(
            p_sphi + (size_t)t * SLOT, p_splo + (size_t)t * SLOT, p_w0hi, p_w0lo, Hh,
            p_h0hi + (size_t)t * SLOT, p_h0lo + (size_t)t * SLOT, p_u0hi, p_u0lo, Hh,
            p_bsum0, nullptr, G4H,
            p_c0, nullptr, p_h0hi + (size_t)(t + 1) * SLOT, p_h0lo + (size_t)(t + 1) * SLOT);
        // layer 1: gates = h0[t+1]@W1^T + h1[t]@U1^T + bsum1 -> fused -> h1[t+1], c1, h1f
        gemm_wm<1><<<dim3(4, NTOT / 128), 256, smemB>>>(
            p_h0hi + (size_t)(t + 1) * SLOT, p_h0lo + (size_t)(t + 1) * SLOT, p_w1hi, p_w1lo, Hh,
            p_h1hi + (size_t)t * SLOT, p_h1lo + (size_t)t * SLOT, p_u1hi, p_u1lo, Hh,
            p_bsum1, nullptr, G4H,
            p_c1, p_h1f, p_h1hi + (size_t)(t + 1) * SLOT, p_h1lo + (size_t)(t + 1) * SLOT);
    }

    ln_kernel<<<(NTOT * 32 + 255) / 256, 256>>>(ln_gamma, ln_beta, out);
}